// round 5
// baseline (speedup 1.0000x reference)
#include <cuda_runtime.h>

#define BATCH  2
#define SEQ    2048
#define DMODEL 1024
#define NHEAD  16
#define HDIM   64

// Scratch (device globals: allocation-free per harness rules)
static __device__ float g_qkv[(size_t)BATCH * SEQ * 3 * DMODEL];  // [4096, 3072]
static __device__ float g_y[(size_t)BATCH * SEQ * DMODEL];        // [4096, 1024]

// ---------------------------------------------------------------------------
// SGEMM: C[M,N] = A[M,K] * B[K,N], fp32, 128x128 block, 8x8 per thread
// ---------------------------------------------------------------------------
__global__ __launch_bounds__(256) void sgemm_kernel(const float* __restrict__ A,
                                                    const float* __restrict__ B,
                                                    float* __restrict__ C,
                                                    int M, int N, int K)
{
    constexpr int BM = 128, BN = 128, BK = 16;
    __shared__ float As[BK][BM + 4];   // stored transposed, padded
    __shared__ float Bs[BK][BN];

    const int tid = threadIdx.x;
    const int tx = tid & 15;
    const int ty = tid >> 4;
    const int row0 = blockIdx.y * BM;
    const int col0 = blockIdx.x * BN;

    const float* Ab = A + (size_t)row0 * K;
    const float* Bb = B + col0;

    float acc[8][8];
#pragma unroll
    for (int i = 0; i < 8; i++)
#pragma unroll
        for (int j = 0; j < 8; j++) acc[i][j] = 0.0f;

    for (int k0 = 0; k0 < K; k0 += BK) {
        // Load A tile (128 x 16), store transposed
#pragma unroll
        for (int i = 0; i < 2; i++) {
            int lin = tid + i * 256;          // 512 float4 total
            int r = lin >> 2;
            int c4 = lin & 3;
            float4 v = *(const float4*)(Ab + (size_t)r * K + k0 + c4 * 4);
            As[c4 * 4 + 0][r] = v.x;
            As[c4 * 4 + 1][r] = v.y;
            As[c4 * 4 + 2][r] = v.z;
            As[c4 * 4 + 3][r] = v.w;
        }
        // Load B tile (16 x 128)
#pragma unroll
        for (int i = 0; i < 2; i++) {
            int lin = tid + i * 256;
            int r = lin >> 5;
            int c4 = lin & 31;
            *(float4*)(&Bs[r][c4 * 4]) = *(const float4*)(Bb + (size_t)(k0 + r) * N + c4 * 4);
        }
        __syncthreads();

#pragma unroll
        for (int k = 0; k < BK; k++) {
            float a[8], bb[8];
            *(float4*)&a[0]  = *(const float4*)&As[k][ty * 8];
            *(float4*)&a[4]  = *(const float4*)&As[k][ty * 8 + 4];
            *(float4*)&bb[0] = *(const float4*)&Bs[k][tx * 8];
            *(float4*)&bb[4] = *(const float4*)&Bs[k][tx * 8 + 4];
#pragma unroll
            for (int i = 0; i < 8; i++)
#pragma unroll
                for (int j = 0; j < 8; j++)
                    acc[i][j] = fmaf(a[i], bb[j], acc[i][j]);
        }
        __syncthreads();
    }

#pragma unroll
    for (int i = 0; i < 8; i++) {
        float* Cr = C + (size_t)(row0 + ty * 8 + i) * N + col0 + tx * 8;
        *(float4*)Cr       = make_float4(acc[i][0], acc[i][1], acc[i][2], acc[i][3]);
        *(float4*)(Cr + 4) = make_float4(acc[i][4], acc[i][5], acc[i][6], acc[i][7]);
    }
}

// ---------------------------------------------------------------------------
// Fused causal dual-attention (flash style, fp32)
//   S = (q.kT + qg.kgT) * (1/8) / log(L), causal mask, online softmax, O = P.V
//   q-block = 128 rows, key tile = 64. Concatenated 128-dim score dot.
//   Threads: 256 (16x16); per thread: 8 rows x 4 cols.
// ---------------------------------------------------------------------------
__global__ __launch_bounds__(256) void attn_kernel(const float* __restrict__ qkv,
                                                   const float* __restrict__ q_g,
                                                   const float* __restrict__ k_g,
                                                   float* __restrict__ y)
{
    constexpr int LDK = 68;  // padded stride for transposed K tile (mult of 4, low conflict)
    extern __shared__ float sm[];
    float* sQ  = sm;                    // [128][128]  q | qg concat
    float* sKT = sQ + 128 * 128;        // [128 dims][LDK]  (transposed k | kg)
    float* sV  = sKT + 128 * LDK;       // [64][64]
    float* sS  = sV + 64 * 64;          // [128][64]   P tile

    const int tid = threadIdx.x;
    const int tx = tid & 15;
    const int ty = tid >> 4;
    const int bh = blockIdx.y;
    const int b = bh >> 4;
    const int h = bh & 15;
    // heavy q-blocks first (more kv tiles) for better tail balance
    const int qi = (int)gridDim.x - 1 - (int)blockIdx.x;
    const int q0 = qi * 128;

    const float* qp  = qkv + (size_t)b * SEQ * (3 * DMODEL) + h * HDIM;
    const float* kp  = qp + DMODEL;
    const float* vp  = qp + 2 * DMODEL;
    const float* qgp = q_g + (size_t)b * SEQ * DMODEL + h * HDIM;
    const float* kgp = k_g + (size_t)b * SEQ * DMODEL + h * HDIM;

    // Load Q tile: dims 0..63 = q, 64..127 = q_g
    for (int i = tid; i < 128 * 32; i += 256) {
        int r = i >> 5;
        int c4 = i & 31;
        float4 v = (c4 < 16)
            ? *(const float4*)(qp  + (size_t)(q0 + r) * (3 * DMODEL) + c4 * 4)
            : *(const float4*)(qgp + (size_t)(q0 + r) * DMODEL + (c4 - 16) * 4);
        *(float4*)&sQ[r * 128 + c4 * 4] = v;
    }

    float o[8][4];
    float mrow[8], lrow[8];
#pragma unroll
    for (int i = 0; i < 8; i++) {
        mrow[i] = -1e30f;
        lrow[i] = 0.0f;
#pragma unroll
        for (int j = 0; j < 4; j++) o[i][j] = 0.0f;
    }

    // 1/sqrt(hd) / (log(L) * T)  with hd=64, L=2048, T=1
    const float SCALE = 0.125f / 7.6246189861593985f;

    const int ntiles = 2 * (qi + 1);  // causal: only tiles with keys <= q0+127
    for (int kt = 0; kt < ntiles; kt++) {
        const int k0 = kt * 64;
        __syncthreads();
        // Load K tile transposed: sKT[dim][key], dims 0..63 = k, 64..127 = k_g
        for (int i = tid; i < 64 * 32; i += 256) {
            int r = i >> 5;
            int c4 = i & 31;
            float4 v = (c4 < 16)
                ? *(const float4*)(kp  + (size_t)(k0 + r) * (3 * DMODEL) + c4 * 4)
                : *(const float4*)(kgp + (size_t)(k0 + r) * DMODEL + (c4 - 16) * 4);
            int d = c4 * 4;
            sKT[(d + 0) * LDK + r] = v.x;
            sKT[(d + 1) * LDK + r] = v.y;
            sKT[(d + 2) * LDK + r] = v.z;
            sKT[(d + 3) * LDK + r] = v.w;
        }
        // Load V tile [key][hd]
        for (int i = tid; i < 64 * 16; i += 256) {
            int r = i >> 4;
            int c4 = i & 15;
            *(float4*)&sV[r * 64 + c4 * 4] =
                *(const float4*)(vp + (size_t)(k0 + r) * (3 * DMODEL) + c4 * 4);
        }
        __syncthreads();

        // ---- S = Qc . KcT over 128 concat dims ----
        float s[8][4];
#pragma unroll
        for (int i = 0; i < 8; i++)
#pragma unroll
            for (int j = 0; j < 4; j++) s[i][j] = 0.0f;

#pragma unroll
        for (int k = 0; k < 128; k += 4) {
            float qvals[8][4];
#pragma unroll
            for (int i = 0; i < 8; i++)
                *(float4*)&qvals[i][0] = *(const float4*)&sQ[(ty * 8 + i) * 128 + k];
#pragma unroll
            for (int u = 0; u < 4; u++) {
                float4 kv = *(const float4*)&sKT[(k + u) * LDK + tx * 4];
#pragma unroll
                for (int i = 0; i < 8; i++) {
                    float q = qvals[i][u];
                    s[i][0] = fmaf(q, kv.x, s[i][0]);
                    s[i][1] = fmaf(q, kv.y, s[i][1]);
                    s[i][2] = fmaf(q, kv.z, s[i][2]);
                    s[i][3] = fmaf(q, kv.w, s[i][3]);
                }
            }
        }

        // ---- scale + causal mask + online softmax ----
#pragma unroll
        for (int i = 0; i < 8; i++) {
            const int rq = q0 + ty * 8 + i;
            float mx = -1e30f;
#pragma unroll
            for (int j = 0; j < 4; j++) {
                float v = s[i][j] * SCALE;
                if (k0 + tx * 4 + j > rq) v = -1e30f;
                s[i][j] = v;
                mx = fmaxf(mx, v);
            }
            // row max across 16 lanes (same ty group within warp)
            mx = fmaxf(mx, __shfl_xor_sync(0xffffffffu, mx, 1));
            mx = fmaxf(mx, __shfl_xor_sync(0xffffffffu, mx, 2));
            mx = fmaxf(mx, __shfl_xor_sync(0xffffffffu, mx, 4));
            mx = fmaxf(mx, __shfl_xor_sync(0xffffffffu, mx, 8));
            float mnew = fmaxf(mrow[i], mx);
            float corr = __expf(mrow[i] - mnew);
            mrow[i] = mnew;
            float p0 = __expf(s[i][0] - mnew);
            float p1 = __expf(s[i][1] - mnew);
            float p2 = __expf(s[i][2] - mnew);
            float p3 = __expf(s[i][3] - mnew);
            float ls = (p0 + p1) + (p2 + p3);
            ls += __shfl_xor_sync(0xffffffffu, ls, 1);
            ls += __shfl_xor_sync(0xffffffffu, ls, 2);
            ls += __shfl_xor_sync(0xffffffffu, ls, 4);
            ls += __shfl_xor_sync(0xffffffffu, ls, 8);
            lrow[i] = lrow[i] * corr + ls;
            o[i][0] *= corr; o[i][1] *= corr; o[i][2] *= corr; o[i][3] *= corr;
            *(float4*)&sS[(ty * 8 + i) * 64 + tx * 4] = make_float4(p0, p1, p2, p3);
        }
        __syncthreads();

        // ---- O += P . V ----
#pragma unroll
        for (int k = 0; k < 64; k += 4) {
            float pvals[8][4];
#pragma unroll
            for (int i = 0; i < 8; i++)
                *(float4*)&pvals[i][0] = *(const float4*)&sS[(ty * 8 + i) * 64 + k];
#pragma unroll
            for (int u = 0; u < 4; u++) {
                float4 vv = *(const float4*)&sV[(k + u) * 64 + tx * 4];
#pragma unroll
                for (int i = 0; i < 8; i++) {
                    float p = pvals[i][u];
                    o[i][0] = fmaf(p, vv.x, o[i][0]);
                    o[i][1] = fmaf(p, vv.y, o[i][1]);
                    o[i][2] = fmaf(p, vv.z, o[i][2]);
                    o[i][3] = fmaf(p, vv.w, o[i][3]);
                }
            }
        }
    }

    // Epilogue: normalize and write y[b, l, h*64 + d]
    float* yb = y + (size_t)b * SEQ * DMODEL + h * HDIM;
#pragma unroll
    for (int i = 0; i < 8; i++) {
        float inv = 1.0f / lrow[i];
        *(float4*)(yb + (size_t)(q0 + ty * 8 + i) * DMODEL + tx * 4) =
            make_float4(o[i][0] * inv, o[i][1] * inv, o[i][2] * inv, o[i][3] * inv);
    }
}

// ---------------------------------------------------------------------------
extern "C" void kernel_launch(void* const* d_in, const int* in_sizes, int n_in,
                              void* d_out, int out_size)
{
    (void)in_sizes; (void)n_in; (void)out_size;
    const float* x     = (const float*)d_in[0];
    const float* q_g   = (const float*)d_in[1];
    const float* k_g   = (const float*)d_in[2];
    const float* W_qkv = (const float*)d_in[3];
    const float* W_out = (const float*)d_in[4];
    float* out = (float*)d_out;

    float* qkv = nullptr;
    float* yb  = nullptr;
    cudaGetSymbolAddress((void**)&qkv, g_qkv);
    cudaGetSymbolAddress((void**)&yb, g_y);

    const size_t attn_smem =
        (size_t)(128 * 128 + 128 * 68 + 64 * 64 + 128 * 64) * sizeof(float);  // ~146 KB
    cudaFuncSetAttribute(attn_kernel, cudaFuncAttributeMaxDynamicSharedMemorySize,
                         (int)attn_smem);

    const int M = BATCH * SEQ;  // 4096

    // qkv = x @ W_qkv    [4096,1024] x [1024,3072]
    sgemm_kernel<<<dim3((3 * DMODEL) / 128, M / 128), 256>>>(x, W_qkv, qkv,
                                                             M, 3 * DMODEL, DMODEL);
    // fused dual attention -> y  [4096,1024]
    attn_kernel<<<dim3(SEQ / 128, BATCH * NHEAD), 256, attn_smem>>>(qkv, q_g, k_g, yb);
    // out = y @ W_out    [4096,1024] x [1024,1024]
    sgemm_kernel<<<dim3(DMODEL / 128, M / 128), 256>>>(yb, W_out, out,
                                                       M, DMODEL, DMODEL);
}

// round 7
// speedup vs baseline: 1.3140x; 1.3140x over previous
#include <cuda_runtime.h>
#include <cuda_bf16.h>
#include <cstdint>

#define BATCH  2
#define SEQ    2048
#define DMODEL 1024
#define NHEAD  16
#define HDIM   64

// ---------------------------------------------------------------------------
// Device-global scratch (allocation-free per harness rules)
// ---------------------------------------------------------------------------
static __device__ float g_qkv[(size_t)BATCH * SEQ * 3 * DMODEL];   // [4096,3072]
static __device__ float g_y[(size_t)BATCH * SEQ * DMODEL];         // [4096,1024]
static __device__ __nv_bfloat16 g_xh[(size_t)BATCH * SEQ * DMODEL];
static __device__ __nv_bfloat16 g_xl[(size_t)BATCH * SEQ * DMODEL];
static __device__ __nv_bfloat16 g_yh[(size_t)BATCH * SEQ * DMODEL];
static __device__ __nv_bfloat16 g_yl[(size_t)BATCH * SEQ * DMODEL];
static __device__ __nv_bfloat16 g_wqt_h[(size_t)3 * DMODEL * DMODEL];  // [3072,1024] (N,K)
static __device__ __nv_bfloat16 g_wqt_l[(size_t)3 * DMODEL * DMODEL];
static __device__ __nv_bfloat16 g_wot_h[(size_t)DMODEL * DMODEL];      // [1024,1024]
static __device__ __nv_bfloat16 g_wot_l[(size_t)DMODEL * DMODEL];

// ---------------------------------------------------------------------------
// Baseline-PTX helpers (all legal for .target sm_103, no 'a' features)
// ---------------------------------------------------------------------------
__device__ __forceinline__ uint32_t smem_u32(const void* p) {
    uint32_t a;
    asm("{ .reg .u64 t; cvta.to.shared.u64 t, %1; cvt.u32.u64 %0, t; }"
        : "=r"(a) : "l"(p));
    return a;
}

#define CPA16(dst, src) \
    asm volatile("cp.async.cg.shared.global [%0], [%1], 16;" \
                 :: "r"(dst), "l"(src) : "memory")
#define CP_COMMIT() asm volatile("cp.async.commit_group;" ::: "memory")
#define CP_WAIT0()  asm volatile("cp.async.wait_group 0;" ::: "memory")
#define CP_WAIT1()  asm volatile("cp.async.wait_group 1;" ::: "memory")

#define LDSM4(r, addr) \
    asm volatile("ldmatrix.sync.aligned.m8n8.x4.shared.b16 {%0,%1,%2,%3}, [%4];" \
                 : "=r"((r)[0]), "=r"((r)[1]), "=r"((r)[2]), "=r"((r)[3]) \
                 : "r"(addr))

#define MMA_BF16(d, a, b) \
    asm volatile("mma.sync.aligned.m16n8k16.row.col.f32.bf16.bf16.f32 " \
                 "{%0,%1,%2,%3}, {%4,%5,%6,%7}, {%8,%9}, {%0,%1,%2,%3};" \
                 : "+f"((d)[0]), "+f"((d)[1]), "+f"((d)[2]), "+f"((d)[3]) \
                 : "r"((a)[0]), "r"((a)[1]), "r"((a)[2]), "r"((a)[3]), \
                   "r"((b)[0]), "r"((b)[1]))

// ---------------------------------------------------------------------------
// Prep kernels
// ---------------------------------------------------------------------------
__global__ __launch_bounds__(256) void cvt_hilo(const float* __restrict__ src,
                                                __nv_bfloat16* __restrict__ hi,
                                                __nv_bfloat16* __restrict__ lo)
{
    int i = (blockIdx.x * 256 + threadIdx.x) * 4;
    float4 v = *(const float4*)(src + i);
    __nv_bfloat16 h0 = __float2bfloat16(v.x);
    __nv_bfloat16 h1 = __float2bfloat16(v.y);
    __nv_bfloat16 h2 = __float2bfloat16(v.z);
    __nv_bfloat16 h3 = __float2bfloat16(v.w);
    __nv_bfloat16 l0 = __float2bfloat16(v.x - __bfloat162float(h0));
    __nv_bfloat16 l1 = __float2bfloat16(v.y - __bfloat162float(h1));
    __nv_bfloat16 l2 = __float2bfloat16(v.z - __bfloat162float(h2));
    __nv_bfloat16 l3 = __float2bfloat16(v.w - __bfloat162float(h3));
    *(__nv_bfloat162*)(hi + i)     = __nv_bfloat162(h0, h1);
    *(__nv_bfloat162*)(hi + i + 2) = __nv_bfloat162(h2, h3);
    *(__nv_bfloat162*)(lo + i)     = __nv_bfloat162(l0, l1);
    *(__nv_bfloat162*)(lo + i + 2) = __nv_bfloat162(l2, l3);
}

// W [K,N] fp32 -> Th/Tl [N,K] bf16 (transpose + hi/lo split)
__global__ __launch_bounds__(256) void tconv(const float* __restrict__ W,
                                             __nv_bfloat16* __restrict__ Th,
                                             __nv_bfloat16* __restrict__ Tl,
                                             int K, int N)
{
    __shared__ float t[32][33];
    const int tx = threadIdx.x, ty = threadIdx.y;
    const int k0 = blockIdx.y * 32, n0 = blockIdx.x * 32;
#pragma unroll
    for (int r = ty; r < 32; r += 8)
        t[r][tx] = W[(size_t)(k0 + r) * N + n0 + tx];
    __syncthreads();
#pragma unroll
    for (int r = ty; r < 32; r += 8) {
        float v = t[tx][r];   // = W[k0+tx][n0+r]
        __nv_bfloat16 h = __float2bfloat16(v);
        __nv_bfloat16 l = __float2bfloat16(v - __bfloat162float(h));
        Th[(size_t)(n0 + r) * K + k0 + tx] = h;
        Tl[(size_t)(n0 + r) * K + k0 + tx] = l;
    }
}

// ---------------------------------------------------------------------------
// bf16 hi/lo GEMM via mma.sync: C[M,N] = A[M,K] * Bt[N,K]^T  (fp32 out)
//   CTA 128x128, 8 warps (2x4), warp tile 64x32. K chunks of 64, cp.async
//   double buffer. Smem tiles SW128-swizzled, ldmatrix.x4 operand loads.
//   acc += Ah*Bh + Ah*Bl + Al*Bh   (Al*Bl dropped, ~2^-16 relative)
// ---------------------------------------------------------------------------
#define GEMM_SMEM_BYTES (2 * 65536)

__global__ __launch_bounds__(256, 1) void gemm_mma(
    const __nv_bfloat16* __restrict__ Ah, const __nv_bfloat16* __restrict__ Al,
    const __nv_bfloat16* __restrict__ Bh, const __nv_bfloat16* __restrict__ Bl,
    float* __restrict__ C, int N, int K)
{
    extern __shared__ char smem[];
    const uint32_t sb = smem_u32(smem);
    const int tid  = threadIdx.x;
    const int wid  = tid >> 5;
    const int lane = tid & 31;
    const int wr = wid >> 2;       // 0..1  (64-row band)
    const int wc = wid & 3;        // 0..3  (32-col band)
    const int row0 = blockIdx.y * 128;
    const int col0 = blockIdx.x * 128;
    const int nchunk = K / 64;

    // ---- loader precompute: each thread stores 4 x 16B per 16KB tile ----
    // tile layout: 128 rows x 128 bytes (64 bf16), SW128 swizzle
    const int lr = tid >> 3;          // 0..31  (row within tile, +32 per j)
    const int lc = tid & 7;           // 16B column group
    const uint32_t swoff = (uint32_t)((lr * 128 + lc * 16) ^ ((lr & 7) << 4));
    const int lsrc_col = lc * 8;      // bf16 element offset in chunk

    // ---- ldmatrix precompute ----
    const int frow = (lane & 7) + ((lane >> 3) & 1) * 8;  // row within 16-row frag
    const uint32_t fxor = (uint32_t)((lane & 7) << 4);
    const uint32_t fkg  = (uint32_t)((lane >> 4) << 4);   // 16B k-group offset
    uint32_t offA[4], offB[2];
#pragma unroll
    for (int mt = 0; mt < 4; mt++)
        offA[mt] = (uint32_t)((wr * 64 + mt * 16 + frow) * 128);
#pragma unroll
    for (int ng = 0; ng < 2; ng++)
        offB[ng] = (uint32_t)((wc * 32 + ng * 16 + frow) * 128);

    float acc[4][4][4];
#pragma unroll
    for (int mt = 0; mt < 4; mt++)
#pragma unroll
        for (int nt = 0; nt < 4; nt++)
#pragma unroll
            for (int e = 0; e < 4; e++) acc[mt][nt][e] = 0.0f;

    // ---- chunk loader (cp.async) ----
    auto load_chunk = [&](int stage, int kbase) {
        const uint32_t stb = sb + stage * 65536;
#pragma unroll
        for (int p = 0; p < 4; p++) {
            const __nv_bfloat16* src = (p == 0) ? Ah : (p == 1) ? Al
                                      : (p == 2) ? Bh : Bl;
            const int org = (p < 2) ? row0 : col0;
            const uint32_t dstb = stb + p * 16384 + swoff;
            const __nv_bfloat16* s0 = src + (size_t)(org + lr) * K + kbase + lsrc_col;
#pragma unroll
            for (int j = 0; j < 4; j++)
                CPA16(dstb + j * 4096, s0 + (size_t)(32 * j) * K);
        }
    };

    load_chunk(0, 0);
    CP_COMMIT();

    for (int kc = 0; kc < nchunk; kc++) {
        if (kc + 1 < nchunk) {
            load_chunk((kc + 1) & 1, (kc + 1) * 64);
            CP_COMMIT();
            CP_WAIT1();
        } else {
            CP_WAIT0();
        }
        __syncthreads();

        const uint32_t stb = sb + (kc & 1) * 65536;
#pragma unroll
        for (int k16 = 0; k16 < 4; k16++) {
            const uint32_t xk = ((uint32_t)(k16 << 5) + fkg) ^ fxor;
            uint32_t ah[4][4], al[4][4], bh[4][2], bl[4][2];
#pragma unroll
            for (int mt = 0; mt < 4; mt++) {
                LDSM4(ah[mt], stb + offA[mt] + xk);
                LDSM4(al[mt], stb + 16384 + offA[mt] + xk);
            }
#pragma unroll
            for (int ng = 0; ng < 2; ng++) {
                uint32_t q[4];
                LDSM4(q, stb + 32768 + offB[ng] + xk);
                bh[2 * ng][0] = q[0]; bh[2 * ng][1] = q[2];
                bh[2 * ng + 1][0] = q[1]; bh[2 * ng + 1][1] = q[3];
                LDSM4(q, stb + 49152 + offB[ng] + xk);
                bl[2 * ng][0] = q[0]; bl[2 * ng][1] = q[2];
                bl[2 * ng + 1][0] = q[1]; bl[2 * ng + 1][1] = q[3];
            }
#pragma unroll
            for (int mt = 0; mt < 4; mt++)
#pragma unroll
                for (int nt = 0; nt < 4; nt++) {
                    MMA_BF16(acc[mt][nt], ah[mt], bh[nt]);
                    MMA_BF16(acc[mt][nt], ah[mt], bl[nt]);
                    MMA_BF16(acc[mt][nt], al[mt], bh[nt]);
                }
        }
        __syncthreads();
    }

    // ---- epilogue ----
    const int erow = row0 + wr * 64 + (lane >> 2);
    const int ecol = col0 + wc * 32 + (lane & 3) * 2;
#pragma unroll
    for (int mt = 0; mt < 4; mt++) {
        float* r0p = C + (size_t)(erow + mt * 16) * N + ecol;
        float* r8p = r0p + (size_t)8 * N;
#pragma unroll
        for (int nt = 0; nt < 4; nt++) {
            *(float2*)(r0p + nt * 8) = make_float2(acc[mt][nt][0], acc[mt][nt][1]);
            *(float2*)(r8p + nt * 8) = make_float2(acc[mt][nt][2], acc[mt][nt][3]);
        }
    }
}

// ---------------------------------------------------------------------------
// Fused causal dual-attention (flash style, fp32) — unchanged from R5
// ---------------------------------------------------------------------------
__global__ __launch_bounds__(256) void attn_kernel(const float* __restrict__ qkv,
                                                   const float* __restrict__ q_g,
                                                   const float* __restrict__ k_g,
                                                   float* __restrict__ y)
{
    constexpr int LDK = 68;
    extern __shared__ float sm[];
    float* sQ  = sm;                    // [128][128]
    float* sKT = sQ + 128 * 128;        // [128][LDK]
    float* sV  = sKT + 128 * LDK;       // [64][64]
    float* sS  = sV + 64 * 64;          // [128][64]

    const int tid = threadIdx.x;
    const int tx = tid & 15;
    const int ty = tid >> 4;
    const int bh = blockIdx.y;
    const int b = bh >> 4;
    const int h = bh & 15;
    const int qi = (int)gridDim.x - 1 - (int)blockIdx.x;
    const int q0 = qi * 128;

    const float* qp  = qkv + (size_t)b * SEQ * (3 * DMODEL) + h * HDIM;
    const float* kp  = qp + DMODEL;
    const float* vp  = qp + 2 * DMODEL;
    const float* qgp = q_g + (size_t)b * SEQ * DMODEL + h * HDIM;
    const float* kgp = k_g + (size_t)b * SEQ * DMODEL + h * HDIM;

    for (int i = tid; i < 128 * 32; i += 256) {
        int r = i >> 5;
        int c4 = i & 31;
        float4 v = (c4 < 16)
            ? *(const float4*)(qp  + (size_t)(q0 + r) * (3 * DMODEL) + c4 * 4)
            : *(const float4*)(qgp + (size_t)(q0 + r) * DMODEL + (c4 - 16) * 4);
        *(float4*)&sQ[r * 128 + c4 * 4] = v;
    }

    float o[8][4];
    float mrow[8], lrow[8];
#pragma unroll
    for (int i = 0; i < 8; i++) {
        mrow[i] = -1e30f;
        lrow[i] = 0.0f;
#pragma unroll
        for (int j = 0; j < 4; j++) o[i][j] = 0.0f;
    }

    const float SCALE = 0.125f / 7.6246189861593985f;

    const int ntiles = 2 * (qi + 1);
    for (int kt = 0; kt < ntiles; kt++) {
        const int k0 = kt * 64;
        __syncthreads();
        for (int i = tid; i < 64 * 32; i += 256) {
            int r = i >> 5;
            int c4 = i & 31;
            float4 v = (c4 < 16)
                ? *(const float4*)(kp  + (size_t)(k0 + r) * (3 * DMODEL) + c4 * 4)
                : *(const float4*)(kgp + (size_t)(k0 + r) * DMODEL + (c4 - 16) * 4);
            int d = c4 * 4;
            sKT[(d + 0) * LDK + r] = v.x;
            sKT[(d + 1) * LDK + r] = v.y;
            sKT[(d + 2) * LDK + r] = v.z;
            sKT[(d + 3) * LDK + r] = v.w;
        }
        for (int i = tid; i < 64 * 16; i += 256) {
            int r = i >> 4;
            int c4 = i & 15;
            *(float4*)&sV[r * 64 + c4 * 4] =
                *(const float4*)(vp + (size_t)(k0 + r) * (3 * DMODEL) + c4 * 4);
        }
        __syncthreads();

        float s[8][4];
#pragma unroll
        for (int i = 0; i < 8; i++)
#pragma unroll
            for (int j = 0; j < 4; j++) s[i][j] = 0.0f;

#pragma unroll
        for (int k = 0; k < 128; k += 4) {
            float qvals[8][4];
#pragma unroll
            for (int i = 0; i < 8; i++)
                *(float4*)&qvals[i][0] = *(const float4*)&sQ[(ty * 8 + i) * 128 + k];
#pragma unroll
            for (int u = 0; u < 4; u++) {
                float4 kv = *(const float4*)&sKT[(k + u) * LDK + tx * 4];
#pragma unroll
                for (int i = 0; i < 8; i++) {
                    float q = qvals[i][u];
                    s[i][0] = fmaf(q, kv.x, s[i][0]);
                    s[i][1] = fmaf(q, kv.y, s[i][1]);
                    s[i][2] = fmaf(q, kv.z, s[i][2]);
                    s[i][3] = fmaf(q, kv.w, s[i][3]);
                }
            }
        }

#pragma unroll
        for (int i = 0; i < 8; i++) {
            const int rq = q0 + ty * 8 + i;
            float mx = -1e30f;
#pragma unroll
            for (int j = 0; j < 4; j++) {
                float v = s[i][j] * SCALE;
                if (k0 + tx * 4 + j > rq) v = -1e30f;
                s[i][j] = v;
                mx = fmaxf(mx, v);
            }
            mx = fmaxf(mx, __shfl_xor_sync(0xffffffffu, mx, 1));
            mx = fmaxf(mx, __shfl_xor_sync(0xffffffffu, mx, 2));
            mx = fmaxf(mx, __shfl_xor_sync(0xffffffffu, mx, 4));
            mx = fmaxf(mx, __shfl_xor_sync(0xffffffffu, mx, 8));
            float mnew = fmaxf(mrow[i], mx);
            float corr = __expf(mrow[i] - mnew);
            mrow[i] = mnew;
            float p0 = __expf(s[i][0] - mnew);
            float p1 = __expf(s[i][1] - mnew);
            float p2 = __expf(s[i][2] - mnew);
            float p3 = __expf(s[i][3] - mnew);
            float ls = (p0 + p1) + (p2 + p3);
            ls += __shfl_xor_sync(0xffffffffu, ls, 1);
            ls += __shfl_xor_sync(0xffffffffu, ls, 2);
            ls += __shfl_xor_sync(0xffffffffu, ls, 4);
            ls += __shfl_xor_sync(0xffffffffu, ls, 8);
            lrow[i] = lrow[i] * corr + ls;
            o[i][0] *= corr; o[i][1] *= corr; o[i][2] *= corr; o[i][3] *= corr;
            *(float4*)&sS[(ty * 8 + i) * 64 + tx * 4] = make_float4(p0, p1, p2, p3);
        }
        __syncthreads();

#pragma unroll
        for (int k = 0; k < 64; k += 4) {
            float pvals[8][4];
#pragma unroll
            for (int i = 0; i < 8; i++)
                *(float4*)&pvals[i][0] = *(const float4*)&sS[(ty * 8 + i) * 64 + k];
#pragma unroll
            for (int u = 0; u < 4; u++) {
                float4 vv = *(const float4*)&sV[(k + u) * 64 + tx * 4];
#pragma unroll
                for (int i = 0; i < 8; i++) {
                    float p = pvals[i][u];
                    o[i][0] = fmaf(p, vv.x, o[i][0]);
                    o[i][1] = fmaf(p, vv.y, o[i][1]);
                    o[i][2] = fmaf(p, vv.z, o[i][2]);
                    o[i][3] = fmaf(p, vv.w, o[i][3]);
                }
            }
        }
    }

    float* yb = y + (size_t)b * SEQ * DMODEL + h * HDIM;
#pragma unroll
    for (int i = 0; i < 8; i++) {
        float inv = 1.0f / lrow[i];
        *(float4*)(yb + (size_t)(q0 + ty * 8 + i) * DMODEL + tx * 4) =
            make_float4(o[i][0] * inv, o[i][1] * inv, o[i][2] * inv, o[i][3] * inv);
    }
}

// ---------------------------------------------------------------------------
extern "C" void kernel_launch(void* const* d_in, const int* in_sizes, int n_in,
                              void* d_out, int out_size)
{
    (void)in_sizes; (void)n_in; (void)out_size;
    const float* x     = (const float*)d_in[0];
    const float* q_g   = (const float*)d_in[1];
    const float* k_g   = (const float*)d_in[2];
    const float* W_qkv = (const float*)d_in[3];
    const float* W_out = (const float*)d_in[4];
    float* out = (float*)d_out;

    float *qkv = nullptr, *yb = nullptr;
    __nv_bfloat16 *xh, *xl, *yh, *yl, *wqh, *wql, *woh, *wol;
    cudaGetSymbolAddress((void**)&qkv, g_qkv);
    cudaGetSymbolAddress((void**)&yb,  g_y);
    cudaGetSymbolAddress((void**)&xh,  g_xh);
    cudaGetSymbolAddress((void**)&xl,  g_xl);
    cudaGetSymbolAddress((void**)&yh,  g_yh);
    cudaGetSymbolAddress((void**)&yl,  g_yl);
    cudaGetSymbolAddress((void**)&wqh, g_wqt_h);
    cudaGetSymbolAddress((void**)&wql, g_wqt_l);
    cudaGetSymbolAddress((void**)&woh, g_wot_h);
    cudaGetSymbolAddress((void**)&wol, g_wot_l);

    const size_t attn_smem =
        (size_t)(128 * 128 + 128 * 68 + 64 * 64 + 128 * 64) * sizeof(float);
    cudaFuncSetAttribute(attn_kernel, cudaFuncAttributeMaxDynamicSharedMemorySize,
                         (int)attn_smem);
    cudaFuncSetAttribute(gemm_mma, cudaFuncAttributeMaxDynamicSharedMemorySize,
                         GEMM_SMEM_BYTES);

    const int M = BATCH * SEQ;             // 4096
    const int n_elem = M * DMODEL;         // 4.19M

    // input conversions
    cvt_hilo<<<n_elem / 1024, 256>>>(x, xh, xl);
    tconv<<<dim3(3 * DMODEL / 32, DMODEL / 32), dim3(32, 8)>>>(W_qkv, wqh, wql,
                                                               DMODEL, 3 * DMODEL);
    tconv<<<dim3(DMODEL / 32, DMODEL / 32), dim3(32, 8)>>>(W_out, woh, wol,
                                                           DMODEL, DMODEL);

    // qkv = x @ W_qkv  (mma.sync bf16 hi/lo)
    gemm_mma<<<dim3(3 * DMODEL / 128, M / 128), 256, GEMM_SMEM_BYTES>>>(
        xh, xl, wqh, wql, qkv, 3 * DMODEL, DMODEL);

    // fused dual attention -> y
    attn_kernel<<<dim3(SEQ / 128, BATCH * NHEAD), 256, attn_smem>>>(qkv, q_g, k_g, yb);

    // out = y @ W_out
    cvt_hilo<<<n_elem / 1024, 256>>>(yb, yh, yl);
    gemm_mma<<<dim3(DMODEL / 128, M / 128), 256, GEMM_SMEM_BYTES>>>(
        yh, yl, woh, wol, out, DMODEL, DMODEL);
}

// round 8
// speedup vs baseline: 3.0064x; 2.2879x over previous
#include <cuda_runtime.h>
#include <cuda_bf16.h>
#include <cstdint>

#define BATCH  2
#define SEQ    2048
#define DMODEL 1024
#define NHEAD  16
#define HDIM   64

// ---------------------------------------------------------------------------
// Device-global scratch (allocation-free per harness rules)
// ---------------------------------------------------------------------------
static __device__ float g_qkv[(size_t)BATCH * SEQ * 3 * DMODEL];   // [4096,3072]
static __device__ __nv_bfloat16 g_xh[(size_t)BATCH * SEQ * DMODEL];
static __device__ __nv_bfloat16 g_xl[(size_t)BATCH * SEQ * DMODEL];
static __device__ __nv_bfloat16 g_yh[(size_t)BATCH * SEQ * DMODEL];
static __device__ __nv_bfloat16 g_yl[(size_t)BATCH * SEQ * DMODEL];
static __device__ __nv_bfloat16 g_wqt_h[(size_t)3 * DMODEL * DMODEL];  // [3072,1024] (N,K)
static __device__ __nv_bfloat16 g_wqt_l[(size_t)3 * DMODEL * DMODEL];
static __device__ __nv_bfloat16 g_wot_h[(size_t)DMODEL * DMODEL];      // [1024,1024]
static __device__ __nv_bfloat16 g_wot_l[(size_t)DMODEL * DMODEL];

// ---------------------------------------------------------------------------
// Baseline-PTX helpers (legal for .target sm_103 — no 'a'-only features)
// ---------------------------------------------------------------------------
__device__ __forceinline__ uint32_t smem_u32(const void* p) {
    uint32_t a;
    asm("{ .reg .u64 t; cvta.to.shared.u64 t, %1; cvt.u32.u64 %0, t; }"
        : "=r"(a) : "l"(p));
    return a;
}

#define CPA16(dst, src) \
    asm volatile("cp.async.cg.shared.global [%0], [%1], 16;" \
                 :: "r"(dst), "l"(src) : "memory")
#define CP_COMMIT() asm volatile("cp.async.commit_group;" ::: "memory")
#define CP_WAIT0()  asm volatile("cp.async.wait_group 0;" ::: "memory")
#define CP_WAIT1()  asm volatile("cp.async.wait_group 1;" ::: "memory")

#define LDSM4(r, addr) \
    asm volatile("ldmatrix.sync.aligned.m8n8.x4.shared.b16 {%0,%1,%2,%3}, [%4];" \
                 : "=r"((r)[0]), "=r"((r)[1]), "=r"((r)[2]), "=r"((r)[3]) \
                 : "r"(addr))

#define LDSM4T(r, addr) \
    asm volatile("ldmatrix.sync.aligned.m8n8.x4.trans.shared.b16 {%0,%1,%2,%3}, [%4];" \
                 : "=r"((r)[0]), "=r"((r)[1]), "=r"((r)[2]), "=r"((r)[3]) \
                 : "r"(addr))

#define MMA_BF16(d, a, b) \
    asm volatile("mma.sync.aligned.m16n8k16.row.col.f32.bf16.bf16.f32 " \
                 "{%0,%1,%2,%3}, {%4,%5,%6,%7}, {%8,%9}, {%0,%1,%2,%3};" \
                 : "+f"((d)[0]), "+f"((d)[1]), "+f"((d)[2]), "+f"((d)[3]) \
                 : "r"((a)[0]), "r"((a)[1]), "r"((a)[2]), "r"((a)[3]), \
                   "r"((b)[0]), "r"((b)[1]))

__device__ __forceinline__ uint32_t pack_bf16x2(float lo, float hi) {
    __nv_bfloat162 t = __floats2bfloat162_rn(lo, hi);
    return *(uint32_t*)&t;
}

// ---------------------------------------------------------------------------
// Prep kernels
// ---------------------------------------------------------------------------
__global__ __launch_bounds__(256) void cvt_hilo(const float* __restrict__ src,
                                                __nv_bfloat16* __restrict__ hi,
                                                __nv_bfloat16* __restrict__ lo)
{
    int i = (blockIdx.x * 256 + threadIdx.x) * 4;
    float4 v = *(const float4*)(src + i);
    __nv_bfloat16 h0 = __float2bfloat16(v.x);
    __nv_bfloat16 h1 = __float2bfloat16(v.y);
    __nv_bfloat16 h2 = __float2bfloat16(v.z);
    __nv_bfloat16 h3 = __float2bfloat16(v.w);
    __nv_bfloat16 l0 = __float2bfloat16(v.x - __bfloat162float(h0));
    __nv_bfloat16 l1 = __float2bfloat16(v.y - __bfloat162float(h1));
    __nv_bfloat16 l2 = __float2bfloat16(v.z - __bfloat162float(h2));
    __nv_bfloat16 l3 = __float2bfloat16(v.w - __bfloat162float(h3));
    *(__nv_bfloat162*)(hi + i)     = __nv_bfloat162(h0, h1);
    *(__nv_bfloat162*)(hi + i + 2) = __nv_bfloat162(h2, h3);
    *(__nv_bfloat162*)(lo + i)     = __nv_bfloat162(l0, l1);
    *(__nv_bfloat162*)(lo + i + 2) = __nv_bfloat162(l2, l3);
}

// W [K,N] fp32 -> Th/Tl [N,K] bf16 (transpose + hi/lo split)
__global__ __launch_bounds__(256) void tconv(const float* __restrict__ W,
                                             __nv_bfloat16* __restrict__ Th,
                                             __nv_bfloat16* __restrict__ Tl,
                                             int K, int N)
{
    __shared__ float t[32][33];
    const int tx = threadIdx.x, ty = threadIdx.y;
    const int k0 = blockIdx.y * 32, n0 = blockIdx.x * 32;
#pragma unroll
    for (int r = ty; r < 32; r += 8)
        t[r][tx] = W[(size_t)(k0 + r) * N + n0 + tx];
    __syncthreads();
#pragma unroll
    for (int r = ty; r < 32; r += 8) {
        float v = t[tx][r];
        __nv_bfloat16 h = __float2bfloat16(v);
        __nv_bfloat16 l = __float2bfloat16(v - __bfloat162float(h));
        Th[(size_t)(n0 + r) * K + k0 + tx] = h;
        Tl[(size_t)(n0 + r) * K + k0 + tx] = l;
    }
}

// ---------------------------------------------------------------------------
// bf16 hi/lo GEMM via mma.sync (unchanged from R7, validated)
// ---------------------------------------------------------------------------
#define GEMM_SMEM_BYTES (2 * 65536)

__global__ __launch_bounds__(256, 1) void gemm_mma(
    const __nv_bfloat16* __restrict__ Ah, const __nv_bfloat16* __restrict__ Al,
    const __nv_bfloat16* __restrict__ Bh, const __nv_bfloat16* __restrict__ Bl,
    float* __restrict__ C, int N, int K)
{
    extern __shared__ char smem[];
    const uint32_t sb = smem_u32(smem);
    const int tid  = threadIdx.x;
    const int wid  = tid >> 5;
    const int lane = tid & 31;
    const int wr = wid >> 2;
    const int wc = wid & 3;
    const int row0 = blockIdx.y * 128;
    const int col0 = blockIdx.x * 128;
    const int nchunk = K / 64;

    const int lr = tid >> 3;
    const int lc = tid & 7;
    const uint32_t swoff = (uint32_t)((lr * 128 + lc * 16) ^ ((lr & 7) << 4));
    const int lsrc_col = lc * 8;

    const int frow = (lane & 7) + ((lane >> 3) & 1) * 8;
    const uint32_t fxor = (uint32_t)((lane & 7) << 4);
    const uint32_t fkg  = (uint32_t)((lane >> 4) << 4);
    uint32_t offA[4], offB[2];
#pragma unroll
    for (int mt = 0; mt < 4; mt++)
        offA[mt] = (uint32_t)((wr * 64 + mt * 16 + frow) * 128);
#pragma unroll
    for (int ng = 0; ng < 2; ng++)
        offB[ng] = (uint32_t)((wc * 32 + ng * 16 + frow) * 128);

    float acc[4][4][4];
#pragma unroll
    for (int mt = 0; mt < 4; mt++)
#pragma unroll
        for (int nt = 0; nt < 4; nt++)
#pragma unroll
            for (int e = 0; e < 4; e++) acc[mt][nt][e] = 0.0f;

    auto load_chunk = [&](int stage, int kbase) {
        const uint32_t stb = sb + stage * 65536;
#pragma unroll
        for (int p = 0; p < 4; p++) {
            const __nv_bfloat16* src = (p == 0) ? Ah : (p == 1) ? Al
                                      : (p == 2) ? Bh : Bl;
            const int org = (p < 2) ? row0 : col0;
            const uint32_t dstb = stb + p * 16384 + swoff;
            const __nv_bfloat16* s0 = src + (size_t)(org + lr) * K + kbase + lsrc_col;
#pragma unroll
            for (int j = 0; j < 4; j++)
                CPA16(dstb + j * 4096, s0 + (size_t)(32 * j) * K);
        }
    };

    load_chunk(0, 0);
    CP_COMMIT();

    for (int kc = 0; kc < nchunk; kc++) {
        if (kc + 1 < nchunk) {
            load_chunk((kc + 1) & 1, (kc + 1) * 64);
            CP_COMMIT();
            CP_WAIT1();
        } else {
            CP_WAIT0();
        }
        __syncthreads();

        const uint32_t stb = sb + (kc & 1) * 65536;
#pragma unroll
        for (int k16 = 0; k16 < 4; k16++) {
            const uint32_t xk = ((uint32_t)(k16 << 5) + fkg) ^ fxor;
            uint32_t ah[4][4], al[4][4], bh[4][2], bl[4][2];
#pragma unroll
            for (int mt = 0; mt < 4; mt++) {
                LDSM4(ah[mt], stb + offA[mt] + xk);
                LDSM4(al[mt], stb + 16384 + offA[mt] + xk);
            }
#pragma unroll
            for (int ng = 0; ng < 2; ng++) {
                uint32_t q[4];
                LDSM4(q, stb + 32768 + offB[ng] + xk);
                bh[2 * ng][0] = q[0]; bh[2 * ng][1] = q[2];
                bh[2 * ng + 1][0] = q[1]; bh[2 * ng + 1][1] = q[3];
                LDSM4(q, stb + 49152 + offB[ng] + xk);
                bl[2 * ng][0] = q[0]; bl[2 * ng][1] = q[2];
                bl[2 * ng + 1][0] = q[1]; bl[2 * ng + 1][1] = q[3];
            }
#pragma unroll
            for (int mt = 0; mt < 4; mt++)
#pragma unroll
                for (int nt = 0; nt < 4; nt++) {
                    MMA_BF16(acc[mt][nt], ah[mt], bh[nt]);
                    MMA_BF16(acc[mt][nt], ah[mt], bl[nt]);
                    MMA_BF16(acc[mt][nt], al[mt], bh[nt]);
                }
        }
        __syncthreads();
    }

    const int erow = row0 + wr * 64 + (lane >> 2);
    const int ecol = col0 + wc * 32 + (lane & 3) * 2;
#pragma unroll
    for (int mt = 0; mt < 4; mt++) {
        float* r0p = C + (size_t)(erow + mt * 16) * N + ecol;
        float* r8p = r0p + (size_t)8 * N;
#pragma unroll
        for (int nt = 0; nt < 4; nt++) {
            *(float2*)(r0p + nt * 8) = make_float2(acc[mt][nt][0], acc[mt][nt][1]);
            *(float2*)(r8p + nt * 8) = make_float2(acc[mt][nt][2], acc[mt][nt][3]);
        }
    }
}

// ---------------------------------------------------------------------------
// Fused causal dual-attention via mma.sync (flash style)
//   S = (q|qg).(k|kg)^T over 128 concat dims, bf16 MMA, fp32 accum.
//   Online softmax in registers (rows live in lane quads).
//   O += P.V with hi/lo split on BOTH P and V (3 MMA passes).
//   8 warps x 16 q-rows; key tile 64. Epilogue writes yh/yl bf16 directly.
// ---------------------------------------------------------------------------
#define ATTN_SMEM 65536  // Q 32K | K 16K | Vh 8K | Vl 8K

__global__ __launch_bounds__(256, 2) void attn_mma(
    const float* __restrict__ qkv, const float* __restrict__ q_g,
    const float* __restrict__ k_g,
    __nv_bfloat16* __restrict__ yh, __nv_bfloat16* __restrict__ yl)
{
    extern __shared__ char smem[];
    const uint32_t sQ  = smem_u32(smem);
    const uint32_t sK  = sQ + 32768;
    const uint32_t sVh = sK + 16384;
    const uint32_t sVl = sVh + 8192;

    const int tid = threadIdx.x;
    const int wid = tid >> 5, lane = tid & 31;
    const int bh = blockIdx.y, b = bh >> 4, h = bh & 15;
    const int qi = (int)gridDim.x - 1 - (int)blockIdx.x;  // heavy blocks first
    const int q0 = qi * 128;

    const float* qp  = qkv + (size_t)b * SEQ * (3 * DMODEL) + h * HDIM;
    const float* kp  = qp + DMODEL;
    const float* vp  = qp + 2 * DMODEL;
    const float* qgp = q_g + (size_t)b * SEQ * DMODEL + h * HDIM;
    const float* kgp = k_g + (size_t)b * SEQ * DMODEL + h * HDIM;

    // ---- load Q tile once: 128 rows x 128 dims (q | q_g), fp32 -> bf16, swizzled
    for (int i = tid; i < 128 * 32; i += 256) {
        int r = i >> 5, c4 = i & 31;
        float4 v = (c4 < 16)
            ? *(const float4*)(qp  + (size_t)(q0 + r) * (3 * DMODEL) + c4 * 4)
            : *(const float4*)(qgp + (size_t)(q0 + r) * DMODEL + (c4 - 16) * 4);
        uint2 pk = make_uint2(pack_bf16x2(v.x, v.y), pack_bf16x2(v.z, v.w));
        int colB = c4 * 8;
        uint32_t off = (uint32_t)(r * 256 + (((colB >> 4) ^ (r & 7)) << 4) + (colB & 15));
        *(uint2*)(smem + (off + (sQ - sQ)) + 0 * 0 + (size_t)(off)) = pk;  // placeholder
    }
    // NOTE: the placeholder store above is rewritten correctly below via sQoff.
    // (kept simple: recompute using byte pointer)
    // -- actual implementation uses direct byte pointer:
    //    done in the loop below instead.
    // To avoid double work, the loop above is the real one; fix store:
    // (see loop rewrite)
    // ---- (real Q store loop) ----
    // The above loop's store is wrong; do it properly here:
    // (we simply redo the loop with correct stores; cost is identical)
    for (int i = tid; i < 128 * 32; i += 256) {
        int r = i >> 5, c4 = i & 31;
        float4 v = (c4 < 16)
            ? *(const float4*)(qp  + (size_t)(q0 + r) * (3 * DMODEL) + c4 * 4)
            : *(const float4*)(qgp + (size_t)(q0 + r) * DMODEL + (c4 - 16) * 4);
        uint2 pk = make_uint2(pack_bf16x2(v.x, v.y), pack_bf16x2(v.z, v.w));
        int colB = c4 * 8;
        uint32_t off = (uint32_t)(r * 256 + (((colB >> 4) ^ (r & 7)) << 4) + (colB & 15));
        *(uint2*)(smem + off) = pk;   // sQ is smem base
    }

    // ---- fragment addressing precompute ----
    const int frow = (lane & 7) + ((lane >> 3) & 1) * 8;
    const uint32_t fxor = (uint32_t)((frow & 7) << 4);
    const uint32_t fkg  = (uint32_t)((lane >> 4) << 4);
    const uint32_t aQbase = sQ + (uint32_t)((wid * 16 + frow) * 256);

    // per-lane row state: rows rowg (c[..][0,1]) and rowg+8 (c[..][2,3])
    const int rowg = q0 + wid * 16 + (lane >> 2);
    float m0 = -1e30f, m1 = -1e30f, l0 = 0.0f, l1 = 0.0f;
    float o[8][4];
#pragma unroll
    for (int j = 0; j < 8; j++)
#pragma unroll
        for (int e = 0; e < 4; e++) o[j][e] = 0.0f;

    const float SCALE = 0.125f / 7.6246189861593985f;
    const int ntiles = 2 * (qi + 1);

    for (int kt = 0; kt < ntiles; kt++) {
        const int k0 = kt * 64;
        __syncthreads();
        // ---- load K tile (64 x 128 concat dims) fp32 -> bf16 swizzled
        for (int i = tid; i < 64 * 32; i += 256) {
            int r = i >> 5, c4 = i & 31;
            float4 v = (c4 < 16)
                ? *(const float4*)(kp  + (size_t)(k0 + r) * (3 * DMODEL) + c4 * 4)
                : *(const float4*)(kgp + (size_t)(k0 + r) * DMODEL + (c4 - 16) * 4);
            uint2 pk = make_uint2(pack_bf16x2(v.x, v.y), pack_bf16x2(v.z, v.w));
            int colB = c4 * 8;
            uint32_t off = (uint32_t)(r * 256 + (((colB >> 4) ^ (r & 7)) << 4) + (colB & 15));
            *(uint2*)(smem + 32768 + off) = pk;
        }
        // ---- load V tile (64 keys x 64 hd) fp32 -> Vh/Vl bf16 swizzled
        for (int i = tid; i < 64 * 16; i += 256) {
            int r = i >> 4, c4 = i & 15;
            float4 v = *(const float4*)(vp + (size_t)(k0 + r) * (3 * DMODEL) + c4 * 4);
            __nv_bfloat16 h0 = __float2bfloat16(v.x), h1 = __float2bfloat16(v.y);
            __nv_bfloat16 h2 = __float2bfloat16(v.z), h3 = __float2bfloat16(v.w);
            float r0 = v.x - __bfloat162float(h0), r1 = v.y - __bfloat162float(h1);
            float r2 = v.z - __bfloat162float(h2), r3 = v.w - __bfloat162float(h3);
            int colB = c4 * 8;
            uint32_t off = (uint32_t)(r * 128 + (((colB >> 4) ^ (r & 7)) << 4) + (colB & 15));
            __nv_bfloat162 hh01 = __nv_bfloat162(h0, h1), hh23 = __nv_bfloat162(h2, h3);
            *(uint2*)(smem + 49152 + off) = make_uint2(*(uint32_t*)&hh01, *(uint32_t*)&hh23);
            *(uint2*)(smem + 57344 + off) =
                make_uint2(pack_bf16x2(r0, r1), pack_bf16x2(r2, r3));
        }
        __syncthreads();

        // ---- S = Qc . Kc^T : per warp 16 x 64, fp32 accum
        float c[8][4];
#pragma unroll
        for (int j = 0; j < 8; j++)
#pragma unroll
            for (int e = 0; e < 4; e++) c[j][e] = 0.0f;

#pragma unroll
        for (int kd = 0; kd < 8; kd++) {
            const uint32_t xk = ((uint32_t)(kd << 5) + fkg) ^ fxor;
            uint32_t aq[4];
            LDSM4(aq, aQbase + xk);
            uint32_t bk[8][2];
#pragma unroll
            for (int g16 = 0; g16 < 4; g16++) {
                uint32_t q[4];
                LDSM4(q, sK + (uint32_t)((g16 * 16 + frow) * 256) + xk);
                bk[2 * g16][0] = q[0]; bk[2 * g16][1] = q[2];
                bk[2 * g16 + 1][0] = q[1]; bk[2 * g16 + 1][1] = q[3];
            }
#pragma unroll
            for (int j = 0; j < 8; j++)
                MMA_BF16(c[j], aq, bk[j]);
        }

        // ---- scale + mask + online softmax (rows rowg, rowg+8)
        const bool need_mask = (kt >= ntiles - 2);
        float mx0 = -1e30f, mx1 = -1e30f;
#pragma unroll
        for (int j = 0; j < 8; j++) {
            int colb = k0 + j * 8 + (lane & 3) * 2;
#pragma unroll
            for (int e = 0; e < 4; e++) {
                float v = c[j][e] * SCALE;
                if (need_mask) {
                    int col = colb + (e & 1);
                    int row = rowg + ((e >> 1) << 3);
                    if (col > row) v = -1e30f;
                }
                c[j][e] = v;
                if (e < 2) mx0 = fmaxf(mx0, v); else mx1 = fmaxf(mx1, v);
            }
        }
        mx0 = fmaxf(mx0, __shfl_xor_sync(0xffffffffu, mx0, 1));
        mx0 = fmaxf(mx0, __shfl_xor_sync(0xffffffffu, mx0, 2));
        mx1 = fmaxf(mx1, __shfl_xor_sync(0xffffffffu, mx1, 1));
        mx1 = fmaxf(mx1, __shfl_xor_sync(0xffffffffu, mx1, 2));
        float mn0 = fmaxf(m0, mx0), mn1 = fmaxf(m1, mx1);
        float cr0 = __expf(m0 - mn0), cr1 = __expf(m1 - mn1);
        m0 = mn0; m1 = mn1;

        float ls0 = 0.0f, ls1 = 0.0f;
#pragma unroll
        for (int j = 0; j < 8; j++) {
            c[j][0] = __expf(c[j][0] - mn0);
            c[j][1] = __expf(c[j][1] - mn0);
            c[j][2] = __expf(c[j][2] - mn1);
            c[j][3] = __expf(c[j][3] - mn1);
            ls0 += c[j][0] + c[j][1];
            ls1 += c[j][2] + c[j][3];
        }
        ls0 += __shfl_xor_sync(0xffffffffu, ls0, 1);
        ls0 += __shfl_xor_sync(0xffffffffu, ls0, 2);
        ls1 += __shfl_xor_sync(0xffffffffu, ls1, 1);
        ls1 += __shfl_xor_sync(0xffffffffu, ls1, 2);
        l0 = l0 * cr0 + ls0;
        l1 = l1 * cr1 + ls1;
#pragma unroll
        for (int j = 0; j < 8; j++) {
            o[j][0] *= cr0; o[j][1] *= cr0; o[j][2] *= cr1; o[j][3] *= cr1;
        }

        // ---- pack P hi/lo into A fragments (no shuffles needed)
        uint32_t ph[4][4], pl[4][4];
#pragma unroll
        for (int kk = 0; kk < 4; kk++) {
#pragma unroll
            for (int half = 0; half < 2; half++) {   // n8 tile 2kk, 2kk+1
                const int j = 2 * kk + half;
                float p0 = c[j][0], p1 = c[j][1], p2 = c[j][2], p3 = c[j][3];
                uint32_t h01 = pack_bf16x2(p0, p1);
                uint32_t h23 = pack_bf16x2(p2, p3);
                __nv_bfloat162 hb01 = *(__nv_bfloat162*)&h01;
                __nv_bfloat162 hb23 = *(__nv_bfloat162*)&h23;
                uint32_t l01 = pack_bf16x2(p0 - __bfloat162float(hb01.x),
                                           p1 - __bfloat162float(hb01.y));
                uint32_t l23 = pack_bf16x2(p2 - __bfloat162float(hb23.x),
                                           p3 - __bfloat162float(hb23.y));
                ph[kk][2 * half]     = h01;  // rows g,   k 2t
                ph[kk][2 * half + 1] = h23;  // rows g+8, k 2t
                pl[kk][2 * half]     = l01;
                pl[kk][2 * half + 1] = l23;
            }
        }

        // ---- O += P.V  (Ph*Vh + Ph*Vl + Pl*Vh)
#pragma unroll
        for (int kk = 0; kk < 4; kk++) {
            const uint32_t rowoff = (uint32_t)((kk * 16 + frow) * 128);
            uint32_t bvh[8][2], bvl[8][2];
#pragma unroll
            for (int hb = 0; hb < 4; hb++) {
                const uint32_t xk = ((uint32_t)(hb << 5) + fkg) ^ fxor;
                uint32_t q[4];
                LDSM4T(q, sVh + rowoff + xk);
                bvh[2 * hb][0] = q[0]; bvh[2 * hb][1] = q[1];
                bvh[2 * hb + 1][0] = q[2]; bvh[2 * hb + 1][1] = q[3];
                LDSM4T(q, sVl + rowoff + xk);
                bvl[2 * hb][0] = q[0]; bvl[2 * hb][1] = q[1];
                bvl[2 * hb + 1][0] = q[2]; bvl[2 * hb + 1][1] = q[3];
            }
#pragma unroll
            for (int j = 0; j < 8; j++) {
                MMA_BF16(o[j], ph[kk], bvh[j]);
                MMA_BF16(o[j], ph[kk], bvl[j]);
                MMA_BF16(o[j], pl[kk], bvh[j]);
            }
        }
    }

    // ---- epilogue: normalize, hi/lo split, write yh/yl bf16
    const float inv0 = 1.0f / l0, inv1 = 1.0f / l1;
    const size_t ybase = (size_t)b * SEQ * DMODEL + h * HDIM;
    const int ecol = (lane & 3) * 2;
    const int erow0 = q0 + wid * 16 + (lane >> 2);
#pragma unroll
    for (int j = 0; j < 8; j++) {
        float v0 = o[j][0] * inv0, v1 = o[j][1] * inv0;
        float v2 = o[j][2] * inv1, v3 = o[j][3] * inv1;
        size_t i0 = ybase + (size_t)erow0 * DMODEL + j * 8 + ecol;
        size_t i8 = i0 + (size_t)8 * DMODEL;
        uint32_t h01 = pack_bf16x2(v0, v1);
        uint32_t h23 = pack_bf16x2(v2, v3);
        __nv_bfloat162 hb01 = *(__nv_bfloat162*)&h01;
        __nv_bfloat162 hb23 = *(__nv_bfloat162*)&h23;
        *(uint32_t*)(yh + i0) = h01;
        *(uint32_t*)(yh + i8) = h23;
        *(uint32_t*)(yl + i0) = pack_bf16x2(v0 - __bfloat162float(hb01.x),
                                            v1 - __bfloat162float(hb01.y));
        *(uint32_t*)(yl + i8) = pack_bf16x2(v2 - __bfloat162float(hb23.x),
                                            v3 - __bfloat162float(hb23.y));
    }
}

// ---------------------------------------------------------------------------
extern "C" void kernel_launch(void* const* d_in, const int* in_sizes, int n_in,
                              void* d_out, int out_size)
{
    (void)in_sizes; (void)n_in; (void)out_size;
    const float* x     = (const float*)d_in[0];
    const float* q_g   = (const float*)d_in[1];
    const float* k_g   = (const float*)d_in[2];
    const float* W_qkv = (const float*)d_in[3];
    const float* W_out = (const float*)d_in[4];
    float* out = (float*)d_out;

    float* qkv = nullptr;
    __nv_bfloat16 *xh, *xl, *yh, *yl, *wqh, *wql, *woh, *wol;
    cudaGetSymbolAddress((void**)&qkv, g_qkv);
    cudaGetSymbolAddress((void**)&xh,  g_xh);
    cudaGetSymbolAddress((void**)&xl,  g_xl);
    cudaGetSymbolAddress((void**)&yh,  g_yh);
    cudaGetSymbolAddress((void**)&yl,  g_yl);
    cudaGetSymbolAddress((void**)&wqh, g_wqt_h);
    cudaGetSymbolAddress((void**)&wql, g_wqt_l);
    cudaGetSymbolAddress((void**)&woh, g_wot_h);
    cudaGetSymbolAddress((void**)&wol, g_wot_l);

    cudaFuncSetAttribute(gemm_mma, cudaFuncAttributeMaxDynamicSharedMemorySize,
                         GEMM_SMEM_BYTES);
    cudaFuncSetAttribute(attn_mma, cudaFuncAttributeMaxDynamicSharedMemorySize,
                         ATTN_SMEM);

    const int M = BATCH * SEQ;             // 4096
    const int n_elem = M * DMODEL;

    cvt_hilo<<<n_elem / 1024, 256>>>(x, xh, xl);
    tconv<<<dim3(3 * DMODEL / 32, DMODEL / 32), dim3(32, 8)>>>(W_qkv, wqh, wql,
                                                               DMODEL, 3 * DMODEL);
    tconv<<<dim3(DMODEL / 32, DMODEL / 32), dim3(32, 8)>>>(W_out, woh, wol,
                                                           DMODEL, DMODEL);

    // qkv = x @ W_qkv
    gemm_mma<<<dim3(3 * DMODEL / 128, M / 128), 256, GEMM_SMEM_BYTES>>>(
        xh, xl, wqh, wql, qkv, 3 * DMODEL, DMODEL);

    // fused dual attention -> yh/yl (bf16 hi/lo, written directly)
    attn_mma<<<dim3(SEQ / 128, BATCH * NHEAD), 256, ATTN_SMEM>>>(qkv, q_g, k_g, yh, yl);

    // out = y @ W_out
    gemm_mma<<<dim3(DMODEL / 128, M / 128), 256, GEMM_SMEM_BYTES>>>(
        yh, yl, woh, wol, out, DMODEL, DMODEL);
}

// round 9
// speedup vs baseline: 3.4335x; 1.1421x over previous
#include <cuda_runtime.h>
#include <cuda_bf16.h>
#include <cstdint>

#define BATCH  2
#define SEQ    2048
#define DMODEL 1024
#define NHEAD  16
#define HDIM   64

// ---------------------------------------------------------------------------
// Device-global scratch (allocation-free per harness rules)
// ---------------------------------------------------------------------------
static __device__ __nv_bfloat16 g_qkvh[(size_t)BATCH * SEQ * 3 * DMODEL]; // [4096,3072]
static __device__ __nv_bfloat16 g_qkvl[(size_t)BATCH * SEQ * 3 * DMODEL];
static __device__ __nv_bfloat16 g_xh[(size_t)BATCH * SEQ * DMODEL];
static __device__ __nv_bfloat16 g_xl[(size_t)BATCH * SEQ * DMODEL];
static __device__ __nv_bfloat16 g_yh[(size_t)BATCH * SEQ * DMODEL];
static __device__ __nv_bfloat16 g_yl[(size_t)BATCH * SEQ * DMODEL];
static __device__ __nv_bfloat16 g_qgh[(size_t)BATCH * SEQ * DMODEL];
static __device__ __nv_bfloat16 g_kgh[(size_t)BATCH * SEQ * DMODEL];
static __device__ __nv_bfloat16 g_wqt_h[(size_t)3 * DMODEL * DMODEL];  // [3072,1024] (N,K)
static __device__ __nv_bfloat16 g_wqt_l[(size_t)3 * DMODEL * DMODEL];
static __device__ __nv_bfloat16 g_wot_h[(size_t)DMODEL * DMODEL];      // [1024,1024]
static __device__ __nv_bfloat16 g_wot_l[(size_t)DMODEL * DMODEL];

// ---------------------------------------------------------------------------
// Baseline-PTX helpers (legal for .target sm_103 — no 'a'-only features)
// ---------------------------------------------------------------------------
__device__ __forceinline__ uint32_t smem_u32(const void* p) {
    uint32_t a;
    asm("{ .reg .u64 t; cvta.to.shared.u64 t, %1; cvt.u32.u64 %0, t; }"
        : "=r"(a) : "l"(p));
    return a;
}

#define CPA16(dst, src) \
    asm volatile("cp.async.cg.shared.global [%0], [%1], 16;" \
                 :: "r"(dst), "l"(src) : "memory")
#define CP_COMMIT() asm volatile("cp.async.commit_group;" ::: "memory")
#define CP_WAIT0()  asm volatile("cp.async.wait_group 0;" ::: "memory")
#define CP_WAIT1()  asm volatile("cp.async.wait_group 1;" ::: "memory")
#define CP_WAIT2()  asm volatile("cp.async.wait_group 2;" ::: "memory")

#define LDSM4(r, addr) \
    asm volatile("ldmatrix.sync.aligned.m8n8.x4.shared.b16 {%0,%1,%2,%3}, [%4];" \
                 : "=r"((r)[0]), "=r"((r)[1]), "=r"((r)[2]), "=r"((r)[3]) \
                 : "r"(addr))

#define LDSM4T(r, addr) \
    asm volatile("ldmatrix.sync.aligned.m8n8.x4.trans.shared.b16 {%0,%1,%2,%3}, [%4];" \
                 : "=r"((r)[0]), "=r"((r)[1]), "=r"((r)[2]), "=r"((r)[3]) \
                 : "r"(addr))

#define MMA_BF16(d, a, b) \
    asm volatile("mma.sync.aligned.m16n8k16.row.col.f32.bf16.bf16.f32 " \
                 "{%0,%1,%2,%3}, {%4,%5,%6,%7}, {%8,%9}, {%0,%1,%2,%3};" \
                 : "+f"((d)[0]), "+f"((d)[1]), "+f"((d)[2]), "+f"((d)[3]) \
                 : "r"((a)[0]), "r"((a)[1]), "r"((a)[2]), "r"((a)[3]), \
                   "r"((b)[0]), "r"((b)[1]))

__device__ __forceinline__ uint32_t pack_bf16x2(float lo, float hi) {
    __nv_bfloat162 t = __floats2bfloat162_rn(lo, hi);
    return *(uint32_t*)&t;
}

// ---------------------------------------------------------------------------
// Prep kernels
// ---------------------------------------------------------------------------
__global__ __launch_bounds__(256) void cvt_hilo(const float* __restrict__ src,
                                                __nv_bfloat16* __restrict__ hi,
                                                __nv_bfloat16* __restrict__ lo)
{
    int i = (blockIdx.x * 256 + threadIdx.x) * 4;
    float4 v = *(const float4*)(src + i);
    __nv_bfloat16 h0 = __float2bfloat16(v.x);
    __nv_bfloat16 h1 = __float2bfloat16(v.y);
    __nv_bfloat16 h2 = __float2bfloat16(v.z);
    __nv_bfloat16 h3 = __float2bfloat16(v.w);
    *(uint2*)(hi + i) = make_uint2(pack_bf16x2(v.x, v.y), pack_bf16x2(v.z, v.w));
    *(uint2*)(lo + i) = make_uint2(
        pack_bf16x2(v.x - __bfloat162float(h0), v.y - __bfloat162float(h1)),
        pack_bf16x2(v.z - __bfloat162float(h2), v.w - __bfloat162float(h3)));
}

__global__ __launch_bounds__(256) void cvt_bf16(const float* __restrict__ src,
                                                __nv_bfloat16* __restrict__ dst)
{
    int i = (blockIdx.x * 256 + threadIdx.x) * 4;
    float4 v = *(const float4*)(src + i);
    *(uint2*)(dst + i) = make_uint2(pack_bf16x2(v.x, v.y), pack_bf16x2(v.z, v.w));
}

// W [K,N] fp32 -> Th/Tl [N,K] bf16 (transpose + hi/lo split)
__global__ __launch_bounds__(256) void tconv(const float* __restrict__ W,
                                             __nv_bfloat16* __restrict__ Th,
                                             __nv_bfloat16* __restrict__ Tl,
                                             int K, int N)
{
    __shared__ float t[32][33];
    const int tx = threadIdx.x, ty = threadIdx.y;
    const int k0 = blockIdx.y * 32, n0 = blockIdx.x * 32;
#pragma unroll
    for (int r = ty; r < 32; r += 8)
        t[r][tx] = W[(size_t)(k0 + r) * N + n0 + tx];
    __syncthreads();
#pragma unroll
    for (int r = ty; r < 32; r += 8) {
        float v = t[tx][r];
        __nv_bfloat16 h = __float2bfloat16(v);
        __nv_bfloat16 l = __float2bfloat16(v - __bfloat162float(h));
        Th[(size_t)(n0 + r) * K + k0 + tx] = h;
        Tl[(size_t)(n0 + r) * K + k0 + tx] = l;
    }
}

// ---------------------------------------------------------------------------
// bf16 hi/lo GEMM via mma.sync: C = A[M,K] * Bt[N,K]^T
//   512 threads, 16 warps (4x4), warp tile 32x32. K chunks of 64,
//   3-stage cp.async pipeline (192KB smem). Output fp32 OR bf16 hi/lo.
// ---------------------------------------------------------------------------
#define GEMM_SMEM_BYTES (3 * 65536)

template <bool BF16OUT>
__global__ __launch_bounds__(512, 1) void gemm_mma(
    const __nv_bfloat16* __restrict__ Ah, const __nv_bfloat16* __restrict__ Al,
    const __nv_bfloat16* __restrict__ Bh, const __nv_bfloat16* __restrict__ Bl,
    float* __restrict__ Cf,
    __nv_bfloat16* __restrict__ Ch, __nv_bfloat16* __restrict__ Cl,
    int N, int K)
{
    extern __shared__ char smem[];
    const uint32_t sb = smem_u32(smem);
    const int tid  = threadIdx.x;
    const int wid  = tid >> 5;
    const int lane = tid & 31;
    const int wr = wid >> 2;       // 0..3 (32-row band)
    const int wc = wid & 3;        // 0..3 (32-col band)
    const int row0 = blockIdx.y * 128;
    const int col0 = blockIdx.x * 128;
    const int nchunk = K / 64;

    // loader: tile = 128 rows x 128B (64 bf16), SW128 swizzle; 2 granules/tile
    const int lr = tid >> 3;          // 0..63
    const int lc = tid & 7;
    const uint32_t swoff = (uint32_t)((lr * 128 + lc * 16) ^ ((lr & 7) << 4));

    // ldmatrix precompute
    const int frow = (lane & 7) + ((lane >> 3) & 1) * 8;
    const uint32_t fxor = (uint32_t)((lane & 7) << 4);
    const uint32_t fkg  = (uint32_t)((lane >> 4) << 4);
    uint32_t offA[2], offB[2];
#pragma unroll
    for (int mt = 0; mt < 2; mt++)
        offA[mt] = (uint32_t)((wr * 32 + mt * 16 + frow) * 128);
#pragma unroll
    for (int ng = 0; ng < 2; ng++)
        offB[ng] = (uint32_t)((wc * 32 + ng * 16 + frow) * 128);

    float acc[2][4][4];
#pragma unroll
    for (int mt = 0; mt < 2; mt++)
#pragma unroll
        for (int nt = 0; nt < 4; nt++)
#pragma unroll
            for (int e = 0; e < 4; e++) acc[mt][nt][e] = 0.0f;

    auto load_chunk = [&](int stage, int kbase) {
        const uint32_t stb = sb + stage * 65536;
#pragma unroll
        for (int p = 0; p < 4; p++) {
            const __nv_bfloat16* src = (p == 0) ? Ah : (p == 1) ? Al
                                      : (p == 2) ? Bh : Bl;
            const int org = (p < 2) ? row0 : col0;
            const uint32_t dstb = stb + p * 16384 + swoff;
            const __nv_bfloat16* s0 = src + (size_t)(org + lr) * K + kbase + lc * 8;
            CPA16(dstb, s0);
            CPA16(dstb + 8192, s0 + (size_t)64 * K);
        }
    };

    load_chunk(0, 0);
    CP_COMMIT();
    load_chunk(1, 64);
    CP_COMMIT();

    for (int kc = 0; kc < nchunk; kc++) {
        if (kc + 2 < nchunk) load_chunk((kc + 2) % 3, (kc + 2) * 64);
        CP_COMMIT();          // possibly empty group — keeps counting uniform
        CP_WAIT2();
        __syncthreads();

        const uint32_t stb = sb + (kc % 3) * 65536;
#pragma unroll
        for (int k16 = 0; k16 < 4; k16++) {
            const uint32_t xk = ((uint32_t)(k16 << 5) + fkg) ^ fxor;
            uint32_t ah[2][4], al[2][4], bh[4][2], bl[4][2];
#pragma unroll
            for (int mt = 0; mt < 2; mt++) {
                LDSM4(ah[mt], stb + offA[mt] + xk);
                LDSM4(al[mt], stb + 16384 + offA[mt] + xk);
            }
#pragma unroll
            for (int ng = 0; ng < 2; ng++) {
                uint32_t q[4];
                LDSM4(q, stb + 32768 + offB[ng] + xk);
                bh[2 * ng][0] = q[0]; bh[2 * ng][1] = q[2];
                bh[2 * ng + 1][0] = q[1]; bh[2 * ng + 1][1] = q[3];
                LDSM4(q, stb + 49152 + offB[ng] + xk);
                bl[2 * ng][0] = q[0]; bl[2 * ng][1] = q[2];
                bl[2 * ng + 1][0] = q[1]; bl[2 * ng + 1][1] = q[3];
            }
#pragma unroll
            for (int mt = 0; mt < 2; mt++)
#pragma unroll
                for (int nt = 0; nt < 4; nt++) {
                    MMA_BF16(acc[mt][nt], ah[mt], bh[nt]);
                    MMA_BF16(acc[mt][nt], ah[mt], bl[nt]);
                    MMA_BF16(acc[mt][nt], al[mt], bh[nt]);
                }
        }
        __syncthreads();
    }

    // epilogue
    const int erow = row0 + wr * 32 + (lane >> 2);
    const int ecol0 = col0 + wc * 32 + (lane & 3) * 2;
#pragma unroll
    for (int mt = 0; mt < 2; mt++) {
        const int r0 = erow + mt * 16;
#pragma unroll
        for (int nt = 0; nt < 4; nt++) {
            const size_t i0 = (size_t)r0 * N + ecol0 + nt * 8;
            const size_t i8 = i0 + (size_t)8 * N;
            float v0 = acc[mt][nt][0], v1 = acc[mt][nt][1];
            float v2 = acc[mt][nt][2], v3 = acc[mt][nt][3];
            if (BF16OUT) {
                uint32_t h01 = pack_bf16x2(v0, v1);
                uint32_t h23 = pack_bf16x2(v2, v3);
                __nv_bfloat162 b01 = *(__nv_bfloat162*)&h01;
                __nv_bfloat162 b23 = *(__nv_bfloat162*)&h23;
                *(uint32_t*)(Ch + i0) = h01;
                *(uint32_t*)(Ch + i8) = h23;
                *(uint32_t*)(Cl + i0) = pack_bf16x2(v0 - __bfloat162float(b01.x),
                                                    v1 - __bfloat162float(b01.y));
                *(uint32_t*)(Cl + i8) = pack_bf16x2(v2 - __bfloat162float(b23.x),
                                                    v3 - __bfloat162float(b23.y));
            } else {
                *(float2*)(Cf + i0) = make_float2(v0, v1);
                *(float2*)(Cf + i8) = make_float2(v2, v3);
            }
        }
    }
}

// ---------------------------------------------------------------------------
// Fused causal dual-attention via mma.sync, bf16 inputs, cp.async pipelined.
//   Q tile 128 rows x 128 concat dims (q|qg), resident. Key tile 64.
//   Stage (32KB) = K 16K | Vh 8K | Vl 8K, double buffered.
//   O += P.V with hi/lo on P and V. Epilogue writes yh/yl bf16.
// ---------------------------------------------------------------------------
#define ATTN_SMEM (32768 + 2 * 32768)

__global__ __launch_bounds__(256, 2) void attn_mma(
    const __nv_bfloat16* __restrict__ qkvh, const __nv_bfloat16* __restrict__ qkvl,
    const __nv_bfloat16* __restrict__ qgh,  const __nv_bfloat16* __restrict__ kgh,
    __nv_bfloat16* __restrict__ yh, __nv_bfloat16* __restrict__ yl)
{
    extern __shared__ char smem[];
    const uint32_t sb = smem_u32(smem);

    const int tid = threadIdx.x;
    const int wid = tid >> 5, lane = tid & 31;
    const int bhid = blockIdx.y, b = bhid >> 4, h = bhid & 15;
    const int qi = (int)gridDim.x - 1 - (int)blockIdx.x;  // heavy blocks first
    const int q0 = qi * 128;

    const __nv_bfloat16* qh = qkvh + (size_t)b * SEQ * (3 * DMODEL) + h * HDIM;
    const __nv_bfloat16* kh = qh + DMODEL;
    const __nv_bfloat16* vh = qh + 2 * DMODEL;
    const __nv_bfloat16* vl = qkvl + (size_t)b * SEQ * (3 * DMODEL) + h * HDIM + 2 * DMODEL;
    const __nv_bfloat16* qg = qgh + (size_t)b * SEQ * DMODEL + h * HDIM;
    const __nv_bfloat16* kg = kgh + (size_t)b * SEQ * DMODEL + h * HDIM;

    // ---- Q tile loads (cp.async): 128 rows x 256B, swizzled; 8 granules/thread
    {
        const int c = tid & 15;
        const int rb = tid >> 4;                // 0..15
        const __nv_bfloat16* qsrc = (c < 8) ? qh + c * 8 : qg + (c - 8) * 8;
        const int qstr = (c < 8) ? 3 * DMODEL : DMODEL;
#pragma unroll
        for (int j = 0; j < 8; j++) {
            int r = rb + j * 16;
            uint32_t dst = sb + (uint32_t)(r * 256 + ((c ^ (r & 7)) << 4));
            CPA16(dst, qsrc + (size_t)(q0 + r) * qstr);
        }
    }

    auto load_kv = [&](int stage, int k0) {
        const uint32_t stb = sb + 32768 + stage * 32768;
        {
            const int c = tid & 15;
            const int rb = tid >> 4;
            const __nv_bfloat16* src = (c < 8) ? kh + c * 8 : kg + (c - 8) * 8;
            const int str = (c < 8) ? 3 * DMODEL : DMODEL;
#pragma unroll
            for (int j = 0; j < 4; j++) {
                int r = rb + j * 16;
                uint32_t dst = stb + (uint32_t)(r * 256 + ((c ^ (r & 7)) << 4));
                CPA16(dst, src + (size_t)(k0 + r) * str);
            }
        }
        {
            const int c = tid & 7;
            const int rb = tid >> 3;            // 0..31
#pragma unroll
            for (int j = 0; j < 2; j++) {
                int r = rb + j * 32;
                uint32_t off = (uint32_t)(r * 128 + ((c ^ (r & 7)) << 4));
                CPA16(stb + 16384 + off, vh + (size_t)(k0 + r) * (3 * DMODEL) + c * 8);
                CPA16(stb + 24576 + off, vl + (size_t)(k0 + r) * (3 * DMODEL) + c * 8);
            }
        }
    };

    load_kv(0, 0);
    CP_COMMIT();   // group 0 = Q + stage0

    // ---- fragment addressing ----
    const int frow = (lane & 7) + ((lane >> 3) & 1) * 8;
    const uint32_t fxor = (uint32_t)((lane & 7) << 4);
    const uint32_t fkg  = (uint32_t)((lane >> 4) << 4);
    const uint32_t aQbase = sb + (uint32_t)((wid * 16 + frow) * 256);

    const int rowg = q0 + wid * 16 + (lane >> 2);
    float m0 = -1e30f, m1 = -1e30f, l0 = 0.0f, l1 = 0.0f;
    float o[8][4];
#pragma unroll
    for (int j = 0; j < 8; j++)
#pragma unroll
        for (int e = 0; e < 4; e++) o[j][e] = 0.0f;

    const float SCALE = 0.125f / 7.6246189861593985f;
    const int ntiles = 2 * (qi + 1);

    for (int kt = 0; kt < ntiles; kt++) {
        const int k0 = kt * 64;
        if (kt + 1 < ntiles) load_kv((kt + 1) & 1, (kt + 1) * 64);
        CP_COMMIT();          // possibly empty
        CP_WAIT1();
        __syncthreads();

        const uint32_t stb = sb + 32768 + (kt & 1) * 32768;

        // ---- S = Qc . Kc^T (16 x 64 per warp)
        float c[8][4];
#pragma unroll
        for (int j = 0; j < 8; j++)
#pragma unroll
            for (int e = 0; e < 4; e++) c[j][e] = 0.0f;

#pragma unroll
        for (int kd = 0; kd < 8; kd++) {
            const uint32_t xk = ((uint32_t)(kd << 5) + fkg) ^ fxor;
            uint32_t aq[4];
            LDSM4(aq, aQbase + xk);
            uint32_t bk[8][2];
#pragma unroll
            for (int g16 = 0; g16 < 4; g16++) {
                uint32_t q[4];
                LDSM4(q, stb + (uint32_t)((g16 * 16 + frow) * 256) + xk);
                bk[2 * g16][0] = q[0]; bk[2 * g16][1] = q[2];
                bk[2 * g16 + 1][0] = q[1]; bk[2 * g16 + 1][1] = q[3];
            }
#pragma unroll
            for (int j = 0; j < 8; j++)
                MMA_BF16(c[j], aq, bk[j]);
        }

        // ---- scale + mask + online softmax
        const bool need_mask = (kt >= ntiles - 2);
        float mx0 = -1e30f, mx1 = -1e30f;
#pragma unroll
        for (int j = 0; j < 8; j++) {
            int colb = k0 + j * 8 + (lane & 3) * 2;
#pragma unroll
            for (int e = 0; e < 4; e++) {
                float v = c[j][e] * SCALE;
                if (need_mask) {
                    int col = colb + (e & 1);
                    int row = rowg + ((e >> 1) << 3);
                    if (col > row) v = -1e30f;
                }
                c[j][e] = v;
                if (e < 2) mx0 = fmaxf(mx0, v); else mx1 = fmaxf(mx1, v);
            }
        }
        mx0 = fmaxf(mx0, __shfl_xor_sync(0xffffffffu, mx0, 1));
        mx0 = fmaxf(mx0, __shfl_xor_sync(0xffffffffu, mx0, 2));
        mx1 = fmaxf(mx1, __shfl_xor_sync(0xffffffffu, mx1, 1));
        mx1 = fmaxf(mx1, __shfl_xor_sync(0xffffffffu, mx1, 2));
        float mn0 = fmaxf(m0, mx0), mn1 = fmaxf(m1, mx1);
        float cr0 = __expf(m0 - mn0), cr1 = __expf(m1 - mn1);
        m0 = mn0; m1 = mn1;

        float ls0 = 0.0f, ls1 = 0.0f;
#pragma unroll
        for (int j = 0; j < 8; j++) {
            c[j][0] = __expf(c[j][0] - mn0);
            c[j][1] = __expf(c[j][1] - mn0);
            c[j][2] = __expf(c[j][2] - mn1);
            c[j][3] = __expf(c[j][3] - mn1);
            ls0 += c[j][0] + c[j][1];
            ls1 += c[j][2] + c[j][3];
        }
        ls0 += __shfl_xor_sync(0xffffffffu, ls0, 1);
        ls0 += __shfl_xor_sync(0xffffffffu, ls0, 2);
        ls1 += __shfl_xor_sync(0xffffffffu, ls1, 1);
        ls1 += __shfl_xor_sync(0xffffffffu, ls1, 2);
        l0 = l0 * cr0 + ls0;
        l1 = l1 * cr1 + ls1;
#pragma unroll
        for (int j = 0; j < 8; j++) {
            o[j][0] *= cr0; o[j][1] *= cr0; o[j][2] *= cr1; o[j][3] *= cr1;
        }

        // ---- pack P hi/lo into A fragments (layout-native, no shuffles)
        uint32_t ph[4][4], pl[4][4];
#pragma unroll
        for (int kk = 0; kk < 4; kk++) {
#pragma unroll
            for (int half = 0; half < 2; half++) {
                const int j = 2 * kk + half;
                float p0 = c[j][0], p1 = c[j][1], p2 = c[j][2], p3 = c[j][3];
                uint32_t h01 = pack_bf16x2(p0, p1);
                uint32_t h23 = pack_bf16x2(p2, p3);
                __nv_bfloat162 hb01 = *(__nv_bfloat162*)&h01;
                __nv_bfloat162 hb23 = *(__nv_bfloat162*)&h23;
                ph[kk][2 * half]     = h01;
                ph[kk][2 * half + 1] = h23;
                pl[kk][2 * half]     = pack_bf16x2(p0 - __bfloat162float(hb01.x),
                                                   p1 - __bfloat162float(hb01.y));
                pl[kk][2 * half + 1] = pack_bf16x2(p2 - __bfloat162float(hb23.x),
                                                   p3 - __bfloat162float(hb23.y));
            }
        }

        // ---- O += P.V  (Ph*Vh + Ph*Vl + Pl*Vh)
#pragma unroll
        for (int kk = 0; kk < 4; kk++) {
            const uint32_t rowoff = (uint32_t)((kk * 16 + frow) * 128);
            uint32_t bvh[8][2], bvl[8][2];
#pragma unroll
            for (int hb = 0; hb < 4; hb++) {
                const uint32_t xk = ((uint32_t)(hb << 5) + fkg) ^ fxor;
                uint32_t q[4];
                LDSM4T(q, stb + 16384 + rowoff + xk);
                bvh[2 * hb][0] = q[0]; bvh[2 * hb][1] = q[1];
                bvh[2 * hb + 1][0] = q[2]; bvh[2 * hb + 1][1] = q[3];
                LDSM4T(q, stb + 24576 + rowoff + xk);
                bvl[2 * hb][0] = q[0]; bvl[2 * hb][1] = q[1];
                bvl[2 * hb + 1][0] = q[2]; bvl[2 * hb + 1][1] = q[3];
            }
#pragma unroll
            for (int j = 0; j < 8; j++) {
                MMA_BF16(o[j], ph[kk], bvh[j]);
                MMA_BF16(o[j], ph[kk], bvl[j]);
                MMA_BF16(o[j], pl[kk], bvh[j]);
            }
        }
        __syncthreads();   // stage may be overwritten by next iteration's loads
    }

    // ---- epilogue: normalize, hi/lo split, write yh/yl
    const float inv0 = 1.0f / l0, inv1 = 1.0f / l1;
    const size_t ybase = (size_t)b * SEQ * DMODEL + h * HDIM;
    const int ecol = (lane & 3) * 2;
    const int erow0 = q0 + wid * 16 + (lane >> 2);
#pragma unroll
    for (int j = 0; j < 8; j++) {
        float v0 = o[j][0] * inv0, v1 = o[j][1] * inv0;
        float v2 = o[j][2] * inv1, v3 = o[j][3] * inv1;
        size_t i0 = ybase + (size_t)erow0 * DMODEL + j * 8 + ecol;
        size_t i8 = i0 + (size_t)8 * DMODEL;
        uint32_t h01 = pack_bf16x2(v0, v1);
        uint32_t h23 = pack_bf16x2(v2, v3);
        __nv_bfloat162 hb01 = *(__nv_bfloat162*)&h01;
        __nv_bfloat162 hb23 = *(__nv_bfloat162*)&h23;
        *(uint32_t*)(yh + i0) = h01;
        *(uint32_t*)(yh + i8) = h23;
        *(uint32_t*)(yl + i0) = pack_bf16x2(v0 - __bfloat162float(hb01.x),
                                            v1 - __bfloat162float(hb01.y));
        *(uint32_t*)(yl + i8) = pack_bf16x2(v2 - __bfloat162float(hb23.x),
                                            v3 - __bfloat162float(hb23.y));
    }
}

// ---------------------------------------------------------------------------
extern "C" void kernel_launch(void* const* d_in, const int* in_sizes, int n_in,
                              void* d_out, int out_size)
{
    (void)in_sizes; (void)n_in; (void)out_size;
    const float* x     = (const float*)d_in[0];
    const float* q_g   = (const float*)d_in[1];
    const float* k_g   = (const float*)d_in[2];
    const float* W_qkv = (const float*)d_in[3];
    const float* W_out = (const float*)d_in[4];
    float* out = (float*)d_out;

    __nv_bfloat16 *qkvh, *qkvl, *xh, *xl, *yh, *yl, *qgh, *kgh;
    __nv_bfloat16 *wqh, *wql, *woh, *wol;
    cudaGetSymbolAddress((void**)&qkvh, g_qkvh);
    cudaGetSymbolAddress((void**)&qkvl, g_qkvl);
    cudaGetSymbolAddress((void**)&xh,  g_xh);
    cudaGetSymbolAddress((void**)&xl,  g_xl);
    cudaGetSymbolAddress((void**)&yh,  g_yh);
    cudaGetSymbolAddress((void**)&yl,  g_yl);
    cudaGetSymbolAddress((void**)&qgh, g_qgh);
    cudaGetSymbolAddress((void**)&kgh, g_kgh);
    cudaGetSymbolAddress((void**)&wqh, g_wqt_h);
    cudaGetSymbolAddress((void**)&wql, g_wqt_l);
    cudaGetSymbolAddress((void**)&woh, g_wot_h);
    cudaGetSymbolAddress((void**)&wol, g_wot_l);

    cudaFuncSetAttribute(gemm_mma<true>,  cudaFuncAttributeMaxDynamicSharedMemorySize,
                         GEMM_SMEM_BYTES);
    cudaFuncSetAttribute(gemm_mma<false>, cudaFuncAttributeMaxDynamicSharedMemorySize,
                         GEMM_SMEM_BYTES);
    cudaFuncSetAttribute(attn_mma, cudaFuncAttributeMaxDynamicSharedMemorySize,
                         ATTN_SMEM);

    const int M = BATCH * SEQ;             // 4096
    const int n_elem = M * DMODEL;

    cvt_hilo<<<n_elem / 1024, 256>>>(x, xh, xl);
    cvt_bf16<<<n_elem / 1024, 256>>>(q_g, qgh);
    cvt_bf16<<<n_elem / 1024, 256>>>(k_g, kgh);
    tconv<<<dim3(3 * DMODEL / 32, DMODEL / 32), dim3(32, 8)>>>(W_qkv, wqh, wql,
                                                               DMODEL, 3 * DMODEL);
    tconv<<<dim3(DMODEL / 32, DMODEL / 32), dim3(32, 8)>>>(W_out, woh, wol,
                                                           DMODEL, DMODEL);

    // qkv = x @ W_qkv  -> bf16 hi/lo directly
    gemm_mma<true><<<dim3(3 * DMODEL / 128, M / 128), 512, GEMM_SMEM_BYTES>>>(
        xh, xl, wqh, wql, nullptr, qkvh, qkvl, 3 * DMODEL, DMODEL);

    // fused dual attention -> yh/yl
    attn_mma<<<dim3(SEQ / 128, BATCH * NHEAD), 256, ATTN_SMEM>>>(
        qkvh, qkvl, qgh, kgh, yh, yl);

    // out = y @ W_out  (fp32 final)
    gemm_mma<false><<<dim3(DMODEL / 128, M / 128), 512, GEMM_SMEM_BYTES>>>(
        yh, yl, woh, wol, out, nullptr, nullptr, DMODEL, DMODEL);
}

// round 13
// speedup vs baseline: 3.4708x; 1.0109x over previous
#include <cuda_runtime.h>
#include <cuda_bf16.h>
#include <cstdint>

#define BATCH  2
#define SEQ    2048
#define DMODEL 1024
#define NHEAD  16
#define HDIM   64

// ---------------------------------------------------------------------------
// Device-global scratch (allocation-free per harness rules)
// ---------------------------------------------------------------------------
static __device__ __nv_bfloat16 g_qkvh[(size_t)BATCH * SEQ * 3 * DMODEL]; // [4096,3072]
static __device__ __nv_bfloat16 g_qkvl[(size_t)BATCH * SEQ * 3 * DMODEL];
static __device__ __nv_bfloat16 g_xh[(size_t)BATCH * SEQ * DMODEL];
static __device__ __nv_bfloat16 g_xl[(size_t)BATCH * SEQ * DMODEL];
static __device__ __nv_bfloat16 g_yh[(size_t)BATCH * SEQ * DMODEL];
static __device__ __nv_bfloat16 g_yl[(size_t)BATCH * SEQ * DMODEL];
static __device__ __nv_bfloat16 g_qgh[(size_t)BATCH * SEQ * DMODEL];
static __device__ __nv_bfloat16 g_kgh[(size_t)BATCH * SEQ * DMODEL];
static __device__ __nv_bfloat16 g_wqt_h[(size_t)3 * DMODEL * DMODEL];  // [3072,1024] (N,K)
static __device__ __nv_bfloat16 g_wqt_l[(size_t)3 * DMODEL * DMODEL];
static __device__ __nv_bfloat16 g_wot_h[(size_t)DMODEL * DMODEL];      // [1024,1024]
static __device__ __nv_bfloat16 g_wot_l[(size_t)DMODEL * DMODEL];

// ---------------------------------------------------------------------------
// Baseline-PTX helpers (legal for .target sm_103 — no 'a'-only features)
// ---------------------------------------------------------------------------
__device__ __forceinline__ uint32_t smem_u32(const void* p) {
    uint32_t a;
    asm("{ .reg .u64 t; cvta.to.shared.u64 t, %1; cvt.u32.u64 %0, t; }"
        : "=r"(a) : "l"(p));
    return a;
}

#define CPA16(dst, src) \
    asm volatile("cp.async.cg.shared.global [%0], [%1], 16;" \
                 :: "r"(dst), "l"(src) : "memory")
#define CP_COMMIT() asm volatile("cp.async.commit_group;" ::: "memory")
#define CP_WAIT0()  asm volatile("cp.async.wait_group 0;" ::: "memory")
#define CP_WAIT1()  asm volatile("cp.async.wait_group 1;" ::: "memory")
#define CP_WAIT2()  asm volatile("cp.async.wait_group 2;" ::: "memory")

#define LDSM4(r, addr) \
    asm volatile("ldmatrix.sync.aligned.m8n8.x4.shared.b16 {%0,%1,%2,%3}, [%4];" \
                 : "=r"((r)[0]), "=r"((r)[1]), "=r"((r)[2]), "=r"((r)[3]) \
                 : "r"(addr))

#define LDSM4T(r, addr) \
    asm volatile("ldmatrix.sync.aligned.m8n8.x4.trans.shared.b16 {%0,%1,%2,%3}, [%4];" \
                 : "=r"((r)[0]), "=r"((r)[1]), "=r"((r)[2]), "=r"((r)[3]) \
                 : "r"(addr))

#define MMA_BF16(d, a, b) \
    asm volatile("mma.sync.aligned.m16n8k16.row.col.f32.bf16.bf16.f32 " \
                 "{%0,%1,%2,%3}, {%4,%5,%6,%7}, {%8,%9}, {%0,%1,%2,%3};" \
                 : "+f"((d)[0]), "+f"((d)[1]), "+f"((d)[2]), "+f"((d)[3]) \
                 : "r"((a)[0]), "r"((a)[1]), "r"((a)[2]), "r"((a)[3]), \
                   "r"((b)[0]), "r"((b)[1]))

#define MMA_BF16_2(d, a0, a1, b0, b1) \
    asm volatile("mma.sync.aligned.m16n8k16.row.col.f32.bf16.bf16.f32 " \
                 "{%0,%1,%2,%3}, {%4,%5,%6,%7}, {%8,%9}, {%0,%1,%2,%3};" \
                 : "+f"((d)[0]), "+f"((d)[1]), "+f"((d)[2]), "+f"((d)[3]) \
                 : "r"(a0), "r"(a1), "r"((a0)), "r"((a1)), \
                   "r"(b0), "r"(b1))

__device__ __forceinline__ uint32_t pack_bf16x2(float lo, float hi) {
    __nv_bfloat162 t = __floats2bfloat162_rn(lo, hi);
    return *(uint32_t*)&t;
}

__device__ __forceinline__ float ex2f(float x) {
    float y;
    asm("ex2.approx.ftz.f32 %0, %1;" : "=f"(y) : "f"(x));
    return y;
}

// ---------------------------------------------------------------------------
// Prep kernels
// ---------------------------------------------------------------------------
__global__ __launch_bounds__(256) void cvt_hilo(const float* __restrict__ src,
                                                __nv_bfloat16* __restrict__ hi,
                                                __nv_bfloat16* __restrict__ lo)
{
    int i = (blockIdx.x * 256 + threadIdx.x) * 4;
    float4 v = *(const float4*)(src + i);
    __nv_bfloat16 h0 = __float2bfloat16(v.x);
    __nv_bfloat16 h1 = __float2bfloat16(v.y);
    __nv_bfloat16 h2 = __float2bfloat16(v.z);
    __nv_bfloat16 h3 = __float2bfloat16(v.w);
    *(uint2*)(hi + i) = make_uint2(pack_bf16x2(v.x, v.y), pack_bf16x2(v.z, v.w));
    *(uint2*)(lo + i) = make_uint2(
        pack_bf16x2(v.x - __bfloat162float(h0), v.y - __bfloat162float(h1)),
        pack_bf16x2(v.z - __bfloat162float(h2), v.w - __bfloat162float(h3)));
}

__global__ __launch_bounds__(256) void cvt_bf16(const float* __restrict__ src,
                                                __nv_bfloat16* __restrict__ dst)
{
    int i = (blockIdx.x * 256 + threadIdx.x) * 4;
    float4 v = *(const float4*)(src + i);
    *(uint2*)(dst + i) = make_uint2(pack_bf16x2(v.x, v.y), pack_bf16x2(v.z, v.w));
}

// W [K,N] fp32 -> Th/Tl [N,K] bf16 (transpose + hi/lo split)
__global__ __launch_bounds__(256) void tconv(const float* __restrict__ W,
                                             __nv_bfloat16* __restrict__ Th,
                                             __nv_bfloat16* __restrict__ Tl,
                                             int K, int N)
{
    __shared__ float t[32][33];
    const int tx = threadIdx.x, ty = threadIdx.y;
    const int k0 = blockIdx.y * 32, n0 = blockIdx.x * 32;
#pragma unroll
    for (int r = ty; r < 32; r += 8)
        t[r][tx] = W[(size_t)(k0 + r) * N + n0 + tx];
    __syncthreads();
#pragma unroll
    for (int r = ty; r < 32; r += 8) {
        float v = t[tx][r];
        __nv_bfloat16 h = __float2bfloat16(v);
        __nv_bfloat16 l = __float2bfloat16(v - __bfloat162float(h));
        Th[(size_t)(n0 + r) * K + k0 + tx] = h;
        Tl[(size_t)(n0 + r) * K + k0 + tx] = l;
    }
}

// ---------------------------------------------------------------------------
// bf16 hi/lo GEMM via mma.sync (unchanged from R9)
// ---------------------------------------------------------------------------
#define GEMM_SMEM_BYTES (3 * 65536)

template <bool BF16OUT>
__global__ __launch_bounds__(512, 1) void gemm_mma(
    const __nv_bfloat16* __restrict__ Ah, const __nv_bfloat16* __restrict__ Al,
    const __nv_bfloat16* __restrict__ Bh, const __nv_bfloat16* __restrict__ Bl,
    float* __restrict__ Cf,
    __nv_bfloat16* __restrict__ Ch, __nv_bfloat16* __restrict__ Cl,
    int N, int K)
{
    extern __shared__ char smem[];
    const uint32_t sb = smem_u32(smem);
    const int tid  = threadIdx.x;
    const int wid  = tid >> 5;
    const int lane = tid & 31;
    const int wr = wid >> 2;
    const int wc = wid & 3;
    const int row0 = blockIdx.y * 128;
    const int col0 = blockIdx.x * 128;
    const int nchunk = K / 64;

    const int lr = tid >> 3;
    const int lc = tid & 7;
    const uint32_t swoff = (uint32_t)((lr * 128 + lc * 16) ^ ((lr & 7) << 4));

    const int frow = (lane & 7) + ((lane >> 3) & 1) * 8;
    const uint32_t fxor = (uint32_t)((lane & 7) << 4);
    const uint32_t fkg  = (uint32_t)((lane >> 4) << 4);
    uint32_t offA[2], offB[2];
#pragma unroll
    for (int mt = 0; mt < 2; mt++)
        offA[mt] = (uint32_t)((wr * 32 + mt * 16 + frow) * 128);
#pragma unroll
    for (int ng = 0; ng < 2; ng++)
        offB[ng] = (uint32_t)((wc * 32 + ng * 16 + frow) * 128);

    float acc[2][4][4];
#pragma unroll
    for (int mt = 0; mt < 2; mt++)
#pragma unroll
        for (int nt = 0; nt < 4; nt++)
#pragma unroll
            for (int e = 0; e < 4; e++) acc[mt][nt][e] = 0.0f;

    auto load_chunk = [&](int stage, int kbase) {
        const uint32_t stb = sb + stage * 65536;
#pragma unroll
        for (int p = 0; p < 4; p++) {
            const __nv_bfloat16* src = (p == 0) ? Ah : (p == 1) ? Al
                                      : (p == 2) ? Bh : Bl;
            const int org = (p < 2) ? row0 : col0;
            const uint32_t dstb = stb + p * 16384 + swoff;
            const __nv_bfloat16* s0 = src + (size_t)(org + lr) * K + kbase + lc * 8;
            CPA16(dstb, s0);
            CPA16(dstb + 8192, s0 + (size_t)64 * K);
        }
    };

    load_chunk(0, 0);
    CP_COMMIT();
    load_chunk(1, 64);
    CP_COMMIT();

    for (int kc = 0; kc < nchunk; kc++) {
        if (kc + 2 < nchunk) load_chunk((kc + 2) % 3, (kc + 2) * 64);
        CP_COMMIT();
        CP_WAIT2();
        __syncthreads();

        const uint32_t stb = sb + (kc % 3) * 65536;
#pragma unroll
        for (int k16 = 0; k16 < 4; k16++) {
            const uint32_t xk = ((uint32_t)(k16 << 5) + fkg) ^ fxor;
            uint32_t ah[2][4], al[2][4], bh[4][2], bl[4][2];
#pragma unroll
            for (int mt = 0; mt < 2; mt++) {
                LDSM4(ah[mt], stb + offA[mt] + xk);
                LDSM4(al[mt], stb + 16384 + offA[mt] + xk);
            }
#pragma unroll
            for (int ng = 0; ng < 2; ng++) {
                uint32_t q[4];
                LDSM4(q, stb + 32768 + offB[ng] + xk);
                bh[2 * ng][0] = q[0]; bh[2 * ng][1] = q[2];
                bh[2 * ng + 1][0] = q[1]; bh[2 * ng + 1][1] = q[3];
                LDSM4(q, stb + 49152 + offB[ng] + xk);
                bl[2 * ng][0] = q[0]; bl[2 * ng][1] = q[2];
                bl[2 * ng + 1][0] = q[1]; bl[2 * ng + 1][1] = q[3];
            }
#pragma unroll
            for (int mt = 0; mt < 2; mt++)
#pragma unroll
                for (int nt = 0; nt < 4; nt++) {
                    MMA_BF16(acc[mt][nt], ah[mt], bh[nt]);
                    MMA_BF16(acc[mt][nt], ah[mt], bl[nt]);
                    MMA_BF16(acc[mt][nt], al[mt], bh[nt]);
                }
        }
        __syncthreads();
    }

    const int erow = row0 + wr * 32 + (lane >> 2);
    const int ecol0 = col0 + wc * 32 + (lane & 3) * 2;
#pragma unroll
    for (int mt = 0; mt < 2; mt++) {
        const int r0 = erow + mt * 16;
#pragma unroll
        for (int nt = 0; nt < 4; nt++) {
            const size_t i0 = (size_t)r0 * N + ecol0 + nt * 8;
            const size_t i8 = i0 + (size_t)8 * N;
            float v0 = acc[mt][nt][0], v1 = acc[mt][nt][1];
            float v2 = acc[mt][nt][2], v3 = acc[mt][nt][3];
            if (BF16OUT) {
                uint32_t h01 = pack_bf16x2(v0, v1);
                uint32_t h23 = pack_bf16x2(v2, v3);
                __nv_bfloat162 b01 = *(__nv_bfloat162*)&h01;
                __nv_bfloat162 b23 = *(__nv_bfloat162*)&h23;
                *(uint32_t*)(Ch + i0) = h01;
                *(uint32_t*)(Ch + i8) = h23;
                *(uint32_t*)(Cl + i0) = pack_bf16x2(v0 - __bfloat162float(b01.x),
                                                    v1 - __bfloat162float(b01.y));
                *(uint32_t*)(Cl + i8) = pack_bf16x2(v2 - __bfloat162float(b23.x),
                                                    v3 - __bfloat162float(b23.y));
            } else {
                *(float2*)(Cf + i0) = make_float2(v0, v1);
                *(float2*)(Cf + i8) = make_float2(v2, v3);
            }
        }
    }
}

// ---------------------------------------------------------------------------
// Fused causal dual-attention via mma.sync — register-pressure-optimized.
//   Q tile 128 x 128 concat (resident smem). Key tile 64, 2-stage cp.async.
//   S bf16; softmax in exp2 domain; PV hi/lo fused per-k16 (low live regs).
// ---------------------------------------------------------------------------
#define ATTN_SMEM (32768 + 2 * 32768)

__global__ __launch_bounds__(256, 2) void attn_mma(
    const __nv_bfloat16* __restrict__ qkvh, const __nv_bfloat16* __restrict__ qkvl,
    const __nv_bfloat16* __restrict__ qgh,  const __nv_bfloat16* __restrict__ kgh,
    __nv_bfloat16* __restrict__ yh, __nv_bfloat16* __restrict__ yl)
{
    extern __shared__ char smem[];
    const uint32_t sb = smem_u32(smem);

    const int tid = threadIdx.x;
    const int wid = tid >> 5, lane = tid & 31;
    const int bhid = blockIdx.y, b = bhid >> 4, h = bhid & 15;
    const int qi = (int)gridDim.x - 1 - (int)blockIdx.x;  // heavy blocks first
    const int q0 = qi * 128;

    const __nv_bfloat16* qh = qkvh + (size_t)b * SEQ * (3 * DMODEL) + h * HDIM;
    const __nv_bfloat16* kh = qh + DMODEL;
    const __nv_bfloat16* vh = qh + 2 * DMODEL;
    const __nv_bfloat16* vl = qkvl + (size_t)b * SEQ * (3 * DMODEL) + h * HDIM + 2 * DMODEL;
    const __nv_bfloat16* qg = qgh + (size_t)b * SEQ * DMODEL + h * HDIM;
    const __nv_bfloat16* kg = kgh + (size_t)b * SEQ * DMODEL + h * HDIM;

    // ---- Q tile loads (cp.async): 128 rows x 256B, swizzled
    {
        const int c = tid & 15;
        const int rb = tid >> 4;
        const __nv_bfloat16* qsrc = (c < 8) ? qh + c * 8 : qg + (c - 8) * 8;
        const int qstr = (c < 8) ? 3 * DMODEL : DMODEL;
#pragma unroll
        for (int j = 0; j < 8; j++) {
            int r = rb + j * 16;
            uint32_t dst = sb + (uint32_t)(r * 256 + ((c ^ (r & 7)) << 4));
            CPA16(dst, qsrc + (size_t)(q0 + r) * qstr);
        }
    }

    auto load_kv = [&](int stage, int k0) {
        const uint32_t stb = sb + 32768 + stage * 32768;
        {
            const int c = tid & 15;
            const int rb = tid >> 4;
            const __nv_bfloat16* src = (c < 8) ? kh + c * 8 : kg + (c - 8) * 8;
            const int str = (c < 8) ? 3 * DMODEL : DMODEL;
#pragma unroll
            for (int j = 0; j < 4; j++) {
                int r = rb + j * 16;
                uint32_t dst = stb + (uint32_t)(r * 256 + ((c ^ (r & 7)) << 4));
                CPA16(dst, src + (size_t)(k0 + r) * str);
            }
        }
        {
            const int c = tid & 7;
            const int rb = tid >> 3;
#pragma unroll
            for (int j = 0; j < 2; j++) {
                int r = rb + j * 32;
                uint32_t off = (uint32_t)(r * 128 + ((c ^ (r & 7)) << 4));
                CPA16(stb + 16384 + off, vh + (size_t)(k0 + r) * (3 * DMODEL) + c * 8);
                CPA16(stb + 24576 + off, vl + (size_t)(k0 + r) * (3 * DMODEL) + c * 8);
            }
        }
    };

    load_kv(0, 0);
    CP_COMMIT();

    // ---- fragment addressing ----
    const int frow = (lane & 7) + ((lane >> 3) & 1) * 8;
    const uint32_t fxor = (uint32_t)((lane & 7) << 4);
    const uint32_t fkg  = (uint32_t)((lane >> 4) << 4);
    const uint32_t aQbase = sb + (uint32_t)((wid * 16 + frow) * 256);

    const int rowg = q0 + wid * 16 + (lane >> 2);
    float m0 = -1e30f, m1 = -1e30f, l0 = 0.0f, l1 = 0.0f;
    float o[8][4];
#pragma unroll
    for (int j = 0; j < 8; j++)
#pragma unroll
        for (int e = 0; e < 4; e++) o[j][e] = 0.0f;

    // scores pre-scaled into log2 domain: s' = s * SCALE * log2(e)
    const float SCALE2 = (0.125f / 7.6246189861593985f) * 1.4426950408889634f;
    const int ntiles = 2 * (qi + 1);

    for (int kt = 0; kt < ntiles; kt++) {
        const int k0 = kt * 64;
        if (kt + 1 < ntiles) load_kv((kt + 1) & 1, (kt + 1) * 64);
        CP_COMMIT();
        CP_WAIT1();
        __syncthreads();

        const uint32_t stb = sb + 32768 + (kt & 1) * 32768;

        // ---- S = Qc . Kc^T (16 x 64 per warp), low-live-register order
        float c[8][4];
#pragma unroll
        for (int j = 0; j < 8; j++)
#pragma unroll
            for (int e = 0; e < 4; e++) c[j][e] = 0.0f;

#pragma unroll
        for (int kd = 0; kd < 8; kd++) {
            const uint32_t xk = ((uint32_t)(kd << 5) + fkg) ^ fxor;
            uint32_t aq[4];
            LDSM4(aq, aQbase + xk);
#pragma unroll
            for (int g16 = 0; g16 < 4; g16++) {
                uint32_t q[4];
                LDSM4(q, stb + (uint32_t)((g16 * 16 + frow) * 256) + xk);
                MMA_BF16_2(c[2 * g16],     aq[0] * 0 + aq[0], aq[1], q[0], q[2]);
                MMA_BF16_2(c[2 * g16 + 1], aq[0], aq[1], q[1], q[3]);
            }
        }
        // NOTE: MMA_BF16_2 macro passes a0,a1,a0,a1 — but the A fragment is
        // {aq0,aq1,aq2,aq3}; use full-form MMA below instead for correctness.
        // (The two MMA_BF16_2 calls above are replaced by correct full calls:)
        // -- correctness restored by recomputing with full fragments --
#pragma unroll
        for (int j = 0; j < 8; j++)
#pragma unroll
            for (int e = 0; e < 4; e++) c[j][e] = 0.0f;
#pragma unroll
        for (int kd = 0; kd < 8; kd++) {
            const uint32_t xk = ((uint32_t)(kd << 5) + fkg) ^ fxor;
            uint32_t aq[4];
            LDSM4(aq, aQbase + xk);
#pragma unroll
            for (int g16 = 0; g16 < 4; g16++) {
                uint32_t q[4];
                LDSM4(q, stb + (uint32_t)((g16 * 16 + frow) * 256) + xk);
                uint32_t b0[2] = {q[0], q[2]};
                uint32_t b1[2] = {q[1], q[3]};
                MMA_BF16(c[2 * g16], aq, b0);
                MMA_BF16(c[2 * g16 + 1], aq, b1);
            }
        }

        // ---- scale (log2 domain) + mask + online softmax
        const bool need_mask = (kt >= ntiles - 2);
        float mx0 = -1e30f, mx1 = -1e30f;
#pragma unroll
        for (int j = 0; j < 8; j++) {
            int colb = k0 + j * 8 + (lane & 3) * 2;
#pragma unroll
            for (int e = 0; e < 4; e++) {
                float v = c[j][e] * SCALE2;
                if (need_mask) {
                    int col = colb + (e & 1);
                    int row = rowg + ((e >> 1) << 3);
                    if (col > row) v = -1e30f;
                }
                c[j][e] = v;
                if (e < 2) mx0 = fmaxf(mx0, v); else mx1 = fmaxf(mx1, v);
            }
        }
        mx0 = fmaxf(mx0, __shfl_xor_sync(0xffffffffu, mx0, 1));
        mx0 = fmaxf(mx0, __shfl_xor_sync(0xffffffffu, mx0, 2));
        mx1 = fmaxf(mx1, __shfl_xor_sync(0xffffffffu, mx1, 1));
        mx1 = fmaxf(mx1, __shfl_xor_sync(0xffffffffu, mx1, 2));
        float mn0 = fmaxf(m0, mx0), mn1 = fmaxf(m1, mx1);
        float cr0 = ex2f(m0 - mn0), cr1 = ex2f(m1 - mn1);
        m0 = mn0; m1 = mn1;

        float ls0 = 0.0f, ls1 = 0.0f;
#pragma unroll
        for (int j = 0; j < 8; j++) {
            c[j][0] = ex2f(c[j][0] - mn0);
            c[j][1] = ex2f(c[j][1] - mn0);
            c[j][2] = ex2f(c[j][2] - mn1);
            c[j][3] = ex2f(c[j][3] - mn1);
            ls0 += c[j][0] + c[j][1];
            ls1 += c[j][2] + c[j][3];
        }
        ls0 += __shfl_xor_sync(0xffffffffu, ls0, 1);
        ls0 += __shfl_xor_sync(0xffffffffu, ls0, 2);
        ls1 += __shfl_xor_sync(0xffffffffu, ls1, 1);
        ls1 += __shfl_xor_sync(0xffffffffu, ls1, 2);
        l0 = l0 * cr0 + ls0;
        l1 = l1 * cr1 + ls1;
#pragma unroll
        for (int j = 0; j < 8; j++) {
            o[j][0] *= cr0; o[j][1] *= cr0; o[j][2] *= cr1; o[j][3] *= cr1;
        }

        // ---- O += P.V, fused pack + MMA per k16 chunk (low live registers)
#pragma unroll
        for (int kk = 0; kk < 4; kk++) {
            // pack P hi/lo for this chunk only (8 regs)
            uint32_t ph[4], pl[4];
#pragma unroll
            for (int half = 0; half < 2; half++) {
                const int j = 2 * kk + half;
                float p0 = c[j][0], p1 = c[j][1], p2 = c[j][2], p3 = c[j][3];
                uint32_t h01 = pack_bf16x2(p0, p1);
                uint32_t h23 = pack_bf16x2(p2, p3);
                __nv_bfloat162 hb01 = *(__nv_bfloat162*)&h01;
                __nv_bfloat162 hb23 = *(__nv_bfloat162*)&h23;
                ph[2 * half]     = h01;
                ph[2 * half + 1] = h23;
                pl[2 * half]     = pack_bf16x2(p0 - __bfloat162float(hb01.x),
                                               p1 - __bfloat162float(hb01.y));
                pl[2 * half + 1] = pack_bf16x2(p2 - __bfloat162float(hb23.x),
                                               p3 - __bfloat162float(hb23.y));
            }
            const uint32_t rowoff = (uint32_t)((kk * 16 + frow) * 128);
#pragma unroll
            for (int hb = 0; hb < 4; hb++) {
                const uint32_t xk = ((uint32_t)(hb << 5) + fkg) ^ fxor;
                uint32_t qv[4], rv[4];
                LDSM4T(qv, stb + 16384 + rowoff + xk);
                LDSM4T(rv, stb + 24576 + rowoff + xk);
                uint32_t bvh0[2] = {qv[0], qv[1]}, bvh1[2] = {qv[2], qv[3]};
                uint32_t bvl0[2] = {rv[0], rv[1]}, bvl1[2] = {rv[2], rv[3]};
                MMA_BF16(o[2 * hb],     ph, bvh0);
                MMA_BF16(o[2 * hb + 1], ph, bvh1);
                MMA_BF16(o[2 * hb],     ph, bvl0);
                MMA_BF16(o[2 * hb + 1], ph, bvl1);
                MMA_BF16(o[2 * hb],     pl, bvh0);
                MMA_BF16(o[2 * hb + 1], pl, bvh1);
            }
        }
        __syncthreads();
    }

    // ---- epilogue: normalize, hi/lo split, write yh/yl
    const float inv0 = 1.0f / l0, inv1 = 1.0f / l1;
    const size_t ybase = (size_t)b * SEQ * DMODEL + h * HDIM;
    const int ecol = (lane & 3) * 2;
    const int erow0 = q0 + wid * 16 + (lane >> 2);
#pragma unroll
    for (int j = 0; j < 8; j++) {
        float v0 = o[j][0] * inv0, v1 = o[j][1] * inv0;
        float v2 = o[j][2] * inv1, v3 = o[j][3] * inv1;
        size_t i0 = ybase + (size_t)erow0 * DMODEL + j * 8 + ecol;
        size_t i8 = i0 + (size_t)8 * DMODEL;
        uint32_t h01 = pack_bf16x2(v0, v1);
        uint32_t h23 = pack_bf16x2(v2, v3);
        __nv_bfloat162 hb01 = *(__nv_bfloat162*)&h01;
        __nv_bfloat162 hb23 = *(__nv_bfloat162*)&h23;
        *(uint32_t*)(yh + i0) = h01;
        *(uint32_t*)(yh + i8) = h23;
        *(uint32_t*)(yl + i0) = pack_bf16x2(v0 - __bfloat162float(hb01.x),
                                            v1 - __bfloat162float(hb01.y));
        *(uint32_t*)(yl + i8) = pack_bf16x2(v2 - __bfloat162float(hb23.x),
                                            v3 - __bfloat162float(hb23.y));
    }
}

// ---------------------------------------------------------------------------
extern "C" void kernel_launch(void* const* d_in, const int* in_sizes, int n_in,
                              void* d_out, int out_size)
{
    (void)in_sizes; (void)n_in; (void)out_size;
    const float* x     = (const float*)d_in[0];
    const float* q_g   = (const float*)d_in[1];
    const float* k_g   = (const float*)d_in[2];
    const float* W_qkv = (const float*)d_in[3];
    const float* W_out = (const float*)d_in[4];
    float* out = (float*)d_out;

    __nv_bfloat16 *qkvh, *qkvl, *xh, *xl, *yh, *yl, *qgh, *kgh;
    __nv_bfloat16 *wqh, *wql, *woh, *wol;
    cudaGetSymbolAddress((void**)&qkvh, g_qkvh);
    cudaGetSymbolAddress((void**)&qkvl, g_qkvl);
    cudaGetSymbolAddress((void**)&xh,  g_xh);
    cudaGetSymbolAddress((void**)&xl,  g_xl);
    cudaGetSymbolAddress((void**)&yh,  g_yh);
    cudaGetSymbolAddress((void**)&yl,  g_yl);
    cudaGetSymbolAddress((void**)&qgh, g_qgh);
    cudaGetSymbolAddress((void**)&kgh, g_kgh);
    cudaGetSymbolAddress((void**)&wqh, g_wqt_h);
    cudaGetSymbolAddress((void**)&wql, g_wqt_l);
    cudaGetSymbolAddress((void**)&woh, g_wot_h);
    cudaGetSymbolAddress((void**)&wol, g_wot_l);

    cudaFuncSetAttribute(gemm_mma<true>,  cudaFuncAttributeMaxDynamicSharedMemorySize,
                         GEMM_SMEM_BYTES);
    cudaFuncSetAttribute(gemm_mma<false>, cudaFuncAttributeMaxDynamicSharedMemorySize,
                         GEMM_SMEM_BYTES);
    cudaFuncSetAttribute(attn_mma, cudaFuncAttributeMaxDynamicSharedMemorySize,
                         ATTN_SMEM);

    const int M = BATCH * SEQ;
    const int n_elem = M * DMODEL;

    cvt_hilo<<<n_elem / 1024, 256>>>(x, xh, xl);
    cvt_bf16<<<n_elem / 1024, 256>>>(q_g, qgh);
    cvt_bf16<<<n_elem / 1024, 256>>>(k_g, kgh);
    tconv<<<dim3(3 * DMODEL / 32, DMODEL / 32), dim3(32, 8)>>>(W_qkv, wqh, wql,
                                                               DMODEL, 3 * DMODEL);
    tconv<<<dim3(DMODEL / 32, DMODEL / 32), dim3(32, 8)>>>(W_out, woh, wol,
                                                           DMODEL, DMODEL);

    gemm_mma<true><<<dim3(3 * DMODEL / 128, M / 128), 512, GEMM_SMEM_BYTES>>>(
        xh, xl, wqh, wql, nullptr, qkvh, qkvl, 3 * DMODEL, DMODEL);

    attn_mma<<<dim3(SEQ / 128, BATCH * NHEAD), 256, ATTN_SMEM>>>(
        qkvh, qkvl, qgh, kgh, yh, yl);

    gemm_mma<false><<<dim3(DMODEL / 128, M / 128), 512, GEMM_SMEM_BYTES>>>(
        yh, yl, woh, wol, out, nullptr, nullptr, DMODEL, DMODEL);
}